// round 11
// baseline (speedup 1.0000x reference)
#include <cuda_runtime.h>
#include <cuda_bf16.h>
#include <math.h>
#include <stdint.h>
#include <string.h>

#define Bq 4
#define Cc 256
#define CIc 128
#define NNp 4096
#define EPSc 1e-5f

// ---------------- scratch (device globals; no allocations allowed) ------------
__device__ float d_wy[Bq * NNp * Cc];                 // [b][c][n] fp32
__device__ __nv_bfloat16 d_xh [Bq * NNp * Cc];        // [b][n][c] bf16 hi (for k_gx_mma)
__device__ __nv_bfloat16 d_xl [Bq * NNp * Cc];        // [b][n][c] bf16 lo
__device__ int8_t d_xq1[Bq * NNp * Cc];               // [b][n][c] s8 hi digit
__device__ int8_t d_xq2[Bq * NNp * Cc];               // [b][n][c] s8 lo digit
__device__ __nv_bfloat16 d_gxh[Bq * CIc * NNp];       // [b][ci][n] bf16 hi
__device__ __nv_bfloat16 d_gxl[Bq * CIc * NNp];       // [b][ci][n] bf16 lo
__device__ __nv_bfloat16 d_yh [Bq * NNp * CIc];       // [b][n][ci] bf16 hi
__device__ __nv_bfloat16 d_yl [Bq * NNp * CIc];       // [b][n][ci] bf16 lo
__device__ __nv_bfloat16 d_gwh[CIc * Cc], d_gwl[CIc * Cc];
__device__ __nv_bfloat16 d_Wwh[Cc * CIc], d_Wwl[Cc * CIc];
__device__ float d_sum[Cc];
__device__ float d_sqs[Cc];
__device__ uint32_t d_xmax;

// ---------------- helpers ------------------------------------------------------
__device__ __forceinline__ uint32_t smem_u32(const void* p) {
    uint32_t a;
    asm("{ .reg .u64 t; cvta.to.shared.u64 t, %1; cvt.u32.u64 %0, t; }"
        : "=r"(a) : "l"(p));
    return a;
}
__device__ __forceinline__ void ldsm4(uint32_t* r, uint32_t addr) {
    asm volatile("ldmatrix.sync.aligned.m8n8.x4.shared.b16 {%0,%1,%2,%3}, [%4];"
                 : "=r"(r[0]), "=r"(r[1]), "=r"(r[2]), "=r"(r[3]) : "r"(addr));
}
__device__ __forceinline__ void mma_bf16(float* c, const uint32_t* a, const uint32_t* b) {
    asm volatile("mma.sync.aligned.m16n8k16.row.col.f32.bf16.bf16.f32 "
                 "{%0,%1,%2,%3}, {%4,%5,%6,%7}, {%8,%9}, {%0,%1,%2,%3};"
                 : "+f"(c[0]), "+f"(c[1]), "+f"(c[2]), "+f"(c[3])
                 : "r"(a[0]), "r"(a[1]), "r"(a[2]), "r"(a[3]), "r"(b[0]), "r"(b[1]));
}
__device__ __forceinline__ void mma_s8(int* c, const uint32_t* a, const uint32_t* b) {
    asm volatile("mma.sync.aligned.m16n8k32.row.col.s32.s8.s8.s32 "
                 "{%0,%1,%2,%3}, {%4,%5,%6,%7}, {%8,%9}, {%0,%1,%2,%3};"
                 : "+r"(c[0]), "+r"(c[1]), "+r"(c[2]), "+r"(c[3])
                 : "r"(a[0]), "r"(a[1]), "r"(a[2]), "r"(a[3]), "r"(b[0]), "r"(b[1]));
}
__device__ __forceinline__ void cp16(uint32_t s, const void* g) {
    asm volatile("cp.async.cg.shared.global [%0], [%1], 16;" :: "r"(s), "l"(g) : "memory");
}
__device__ __forceinline__ void cp_commit() {
    asm volatile("cp.async.commit_group;" ::: "memory");
}
__device__ __forceinline__ void cp_wait0() {
    asm volatile("cp.async.wait_group 0;" ::: "memory");
}
// pack(x->low, y->high) bf16x2, plus residual pack
__device__ __forceinline__ void split2(float x, float y, uint32_t& h, uint32_t& l) {
    __nv_bfloat16 xh = __float2bfloat16(x);
    __nv_bfloat16 yh = __float2bfloat16(y);
    __nv_bfloat162 hp; hp.x = xh; hp.y = yh;
    h = *reinterpret_cast<uint32_t*>(&hp);
    float xr = x - __bfloat162float(xh);
    float yr = y - __bfloat162float(yh);
    __nv_bfloat162 lp = __floats2bfloat162_rn(xr, yr);
    l = *reinterpret_cast<uint32_t*>(&lp);
}

// generic [128 rows][64 col] bf16 chunk loader, XOR-swizzled, gmem row stride gs
__device__ __forceinline__ void cp_chunkS(uint32_t sdst, const __nv_bfloat16* g, int gs) {
    int t = threadIdx.x;
#pragma unroll
    for (int i = 0; i < 4; i++) {
        int e = t + (i << 8);
        int r = e >> 3, u = e & 7;
        uint32_t su = (uint32_t)(u ^ (r & 7));
        cp16(sdst + ((uint32_t)r << 7) + (su << 4), g + (size_t)r * gs + u * 8);
    }
}

// ---------------- absmax (deterministic) ---------------------------------------
__global__ void k_reset() { d_xmax = 0u; }

__global__ void k_absmax(const float* __restrict__ x) {
    __shared__ uint32_t red[256];
    int t = threadIdx.x;
    size_t base = (size_t)blockIdx.x * 4096 + t;      // 1024 blocks
    uint32_t m = 0;
#pragma unroll
    for (int j = 0; j < 16; j++)
        m = max(m, __float_as_uint(fabsf(x[base + (size_t)j * 256])));
    red[t] = m;
    __syncthreads();
#pragma unroll
    for (int o = 128; o > 0; o >>= 1) {
        if (t < o) red[t] = max(red[t], red[t + o]);
        __syncthreads();
    }
    if (t == 0) atomicMax(&d_xmax, red[0]);
}

// ---------------- transpose x[b][c][n] -> xh/xl + xq1/xq2 [b][n][c] -----------
__global__ void k_transpose(const float* __restrict__ x) {
    __shared__ float tile[32][33];
    int b  = blockIdx.z;
    int n0 = blockIdx.x * 32;
    int c0 = blockIdx.y * 32;
    int tx = threadIdx.x, ty = threadIdx.y;            // 32 x 8
    const float* xb = x + (size_t)b * Cc * NNp;
#pragma unroll
    for (int j = 0; j < 4; j++) {
        int c = c0 + ty + 8 * j;
        tile[ty + 8 * j][tx] = xb[(size_t)c * NNp + n0 + tx];
    }
    __syncthreads();
    float um = __uint_as_float(d_xmax);
    float inv = 16256.f / fmaxf(um * 1.02f, 1e-20f);
    __nv_bfloat16* xhb = d_xh + (size_t)b * NNp * Cc;
    __nv_bfloat16* xlb = d_xl + (size_t)b * NNp * Cc;
    int8_t* x1b = d_xq1 + (size_t)b * NNp * Cc;
    int8_t* x2b = d_xq2 + (size_t)b * NNp * Cc;
#pragma unroll
    for (int j = 0; j < 4; j++) {
        int n = n0 + ty + 8 * j;
        float v = tile[tx][ty + 8 * j];
        size_t o = (size_t)n * Cc + c0 + tx;
        __nv_bfloat16 h = __float2bfloat16(v);
        xhb[o] = h;
        xlb[o] = __float2bfloat16(v - __bfloat162float(h));
        int q = __float2int_rn(v * inv);
        q = min(max(q, -16256), 16256);
        int hi = (q + 64) >> 7;
        x1b[o] = (int8_t)hi;
        x2b[o] = (int8_t)(q - (hi << 7));
    }
}

// ---------------- weight splits ------------------------------------------------
__global__ void k_split_w(const float* __restrict__ gw, const float* __restrict__ Ww) {
    int i = blockIdx.x * 256 + threadIdx.x;        // 128 blocks x 256 = 32768
    float v = gw[i];
    __nv_bfloat16 h = __float2bfloat16(v);
    d_gwh[i] = h; d_gwl[i] = __float2bfloat16(v - __bfloat162float(h));
    v = Ww[i];
    h = __float2bfloat16(v);
    d_Wwh[i] = h; d_Wwl[i] = __float2bfloat16(v - __bfloat162float(h));
}

// ---------------- gxT[b][ci][n] = g_w x + g_b  (split-bf16 mma) ---------------
#define GXA_H 0u
#define GXA_L 65536u
#define GXB0  131072u
#define GSMEM 196608

__global__ __launch_bounds__(256, 1) void k_gx_mma(const float* __restrict__ gb) {
    extern __shared__ char sm[];
    uint32_t sb = smem_u32(sm);
    int t = threadIdx.x, L = t & 31, wid = t >> 5;
    int bx = blockIdx.x;
    int b  = bx >> 5;
    int n0 = (bx & 31) << 7;
    const __nv_bfloat16* Bh = d_xh + ((size_t)b * NNp + n0) * Cc;
    const __nv_bfloat16* Bl = d_xl + ((size_t)b * NNp + n0) * Cc;

#pragma unroll
    for (int i = 0; i < 16; i++) {
        int e = t + (i << 8);
        int r = e >> 5, u = e & 31;
        uint32_t su = (uint32_t)(u ^ (r & 7));
        cp16(sb + GXA_H + ((uint32_t)r << 9) + (su << 4), d_gwh + (size_t)r * Cc + u * 8);
        cp16(sb + GXA_L + ((uint32_t)r << 9) + (su << 4), d_gwl + (size_t)r * Cc + u * 8);
    }
    cp_chunkS(sb + GXB0, Bh, Cc);
    cp_chunkS(sb + GXB0 + 16384u, Bl, Cc);
    cp_commit();

    uint32_t qrow = (uint32_t)(16 * wid + (L & 15));
    uint32_t qsw  = qrow & 7;
    uint32_t qk8  = (uint32_t)(L >> 4);
    uint32_t krow = (uint32_t)((L & 7) + ((L >> 4) << 3));
    uint32_t ksw  = krow & 7;
    uint32_t bk   = (uint32_t)((L >> 3) & 1);

    float acc[16][4];
#pragma unroll
    for (int j = 0; j < 16; j++)
#pragma unroll
        for (int q = 0; q < 4; q++) acc[j][q] = 0.f;

    for (int kc = 0; kc < 4; kc++) {
        cp_wait0();
        __syncthreads();
        if (kc < 3) {
            uint32_t nb = GXB0 + ((uint32_t)((kc + 1) & 1)) * 32768u;
            cp_chunkS(sb + nb, Bh + (kc + 1) * 64, Cc);
            cp_chunkS(sb + nb + 16384u, Bl + (kc + 1) * 64, Cc);
            cp_commit();
        }
        uint32_t bbh = sb + GXB0 + ((uint32_t)(kc & 1)) * 32768u;
        uint32_t bbl = bbh + 16384u;
#pragma unroll
        for (int ks = 0; ks < 4; ks++) {
            uint32_t ah[4], al[4], br[8][4];
            uint32_t ku = (uint32_t)(kc * 8 + ks * 2) + qk8;
            uint32_t qa = sb + GXA_H + (qrow << 9) + ((ku ^ qsw) << 4);
            ldsm4(ah, qa);
            ldsm4(al, qa + 65536u);
            uint32_t bsw = (((uint32_t)(ks * 2) + bk) ^ ksw) << 4;
#pragma unroll
            for (int jj = 0; jj < 8; jj++)
                ldsm4(br[jj], bbh + (((uint32_t)(16 * jj) + krow) << 7) + bsw);
#pragma unroll
            for (int j = 0; j < 16; j++) mma_bf16(acc[j], ah, &br[j >> 1][(j & 1) * 2]);
#pragma unroll
            for (int j = 0; j < 16; j++) mma_bf16(acc[j], al, &br[j >> 1][(j & 1) * 2]);
#pragma unroll
            for (int jj = 0; jj < 8; jj++)
                ldsm4(br[jj], bbl + (((uint32_t)(16 * jj) + krow) << 7) + bsw);
#pragma unroll
            for (int j = 0; j < 16; j++) mma_bf16(acc[j], ah, &br[j >> 1][(j & 1) * 2]);
        }
    }

    int ci0 = 16 * wid + (L >> 2);
    float b0 = gb[ci0], b1 = gb[ci0 + 8];
    __nv_bfloat16* oh = d_gxh + ((size_t)b * CIc + ci0) * NNp + n0;
    __nv_bfloat16* ol = d_gxl + ((size_t)b * CIc + ci0) * NNp + n0;
#pragma unroll
    for (int j = 0; j < 16; j++) {
        int col = 8 * j + 2 * (L & 3);
        uint32_t h, l;
        split2(acc[j][0] + b0, acc[j][1] + b0, h, l);
        *reinterpret_cast<uint32_t*>(oh + col) = h;
        *reinterpret_cast<uint32_t*>(ol + col) = l;
        split2(acc[j][2] + b1, acc[j][3] + b1, h, l);
        *reinterpret_cast<uint32_t*>(oh + 8 * NNp + col) = h;
        *reinterpret_cast<uint32_t*>(ol + 8 * NNp + col) = l;
    }
}

// ---------------- wy[b][c][n] = W_w y + W_b  (split-bf16 mma) -----------------
__global__ __launch_bounds__(256, 1) void k_wy_mma(const float* __restrict__ Wb) {
    extern __shared__ char sm[];
    uint32_t sb = smem_u32(sm);
    int t = threadIdx.x, L = t & 31, wid = t >> 5;
    int bx = blockIdx.x;
    int b  = bx >> 5;
    int n0 = (bx & 31) << 7;
    const __nv_bfloat16* Bh = d_yh + ((size_t)b * NNp + n0) * CIc;
    const __nv_bfloat16* Bl = d_yl + ((size_t)b * NNp + n0) * CIc;

#pragma unroll
    for (int i = 0; i < 16; i++) {
        int e = t + (i << 8);
        int r = e >> 4, u = e & 15;
        uint32_t su = (uint32_t)(u ^ (r & 7));
        cp16(sb + GXA_H + ((uint32_t)r << 8) + (su << 4), d_Wwh + (size_t)r * CIc + u * 8);
        cp16(sb + GXA_L + ((uint32_t)r << 8) + (su << 4), d_Wwl + (size_t)r * CIc + u * 8);
    }
    cp_chunkS(sb + GXB0, Bh, CIc);
    cp_chunkS(sb + GXB0 + 16384u, Bl, CIc);
    cp_commit();

    uint32_t arow0 = (uint32_t)(32 * wid + (L & 15));
    uint32_t qk8   = (uint32_t)(L >> 4);
    uint32_t krow  = (uint32_t)((L & 7) + ((L >> 4) << 3));
    uint32_t ksw   = krow & 7;
    uint32_t bk    = (uint32_t)((L >> 3) & 1);

    float acc[2][16][4];
#pragma unroll
    for (int mt = 0; mt < 2; mt++)
#pragma unroll
        for (int j = 0; j < 16; j++)
#pragma unroll
            for (int q = 0; q < 4; q++) acc[mt][j][q] = 0.f;

    for (int kc = 0; kc < 2; kc++) {
        cp_wait0();
        __syncthreads();
        if (kc < 1) {
            cp_chunkS(sb + GXB0 + 32768u, Bh + 64, CIc);
            cp_chunkS(sb + GXB0 + 49152u, Bl + 64, CIc);
            cp_commit();
        }
        uint32_t bbh = sb + GXB0 + ((uint32_t)kc) * 32768u;
        uint32_t bbl = bbh + 16384u;
#pragma unroll
        for (int ks = 0; ks < 4; ks++) {
            uint32_t ah[2][4], al[2][4], br[8][4];
            uint32_t ku = (uint32_t)(kc * 8 + ks * 2) + qk8;
#pragma unroll
            for (int mt = 0; mt < 2; mt++) {
                uint32_t ar = arow0 + 16u * (uint32_t)mt;
                uint32_t qa = sb + GXA_H + (ar << 8) + ((ku ^ (ar & 7)) << 4);
                ldsm4(ah[mt], qa);
                ldsm4(al[mt], qa + 65536u);
            }
            uint32_t bsw = (((uint32_t)(ks * 2) + bk) ^ ksw) << 4;
#pragma unroll
            for (int jj = 0; jj < 8; jj++)
                ldsm4(br[jj], bbh + (((uint32_t)(16 * jj) + krow) << 7) + bsw);
#pragma unroll
            for (int mt = 0; mt < 2; mt++)
#pragma unroll
                for (int j = 0; j < 16; j++)
                    mma_bf16(acc[mt][j], ah[mt], &br[j >> 1][(j & 1) * 2]);
#pragma unroll
            for (int mt = 0; mt < 2; mt++)
#pragma unroll
                for (int j = 0; j < 16; j++)
                    mma_bf16(acc[mt][j], al[mt], &br[j >> 1][(j & 1) * 2]);
#pragma unroll
            for (int jj = 0; jj < 8; jj++)
                ldsm4(br[jj], bbl + (((uint32_t)(16 * jj) + krow) << 7) + bsw);
#pragma unroll
            for (int mt = 0; mt < 2; mt++)
#pragma unroll
                for (int j = 0; j < 16; j++)
                    mma_bf16(acc[mt][j], ah[mt], &br[j >> 1][(j & 1) * 2]);
        }
    }

    int c0 = 32 * wid + (L >> 2);
#pragma unroll
    for (int mt = 0; mt < 2; mt++) {
        int ca = c0 + 16 * mt, cb = ca + 8;
        float ba = Wb[ca], bb2 = Wb[cb];
        float* oa = d_wy + ((size_t)b * Cc + ca) * NNp + n0;
        float* ob = d_wy + ((size_t)b * Cc + cb) * NNp + n0;
#pragma unroll
        for (int j = 0; j < 16; j++) {
            int col = 8 * j + 2 * (L & 3);
            float2 v;
            v.x = acc[mt][j][0] + ba; v.y = acc[mt][j][1] + ba;
            *reinterpret_cast<float2*>(oa + col) = v;
            v.x = acc[mt][j][2] + bb2; v.y = acc[mt][j][3] + bb2;
            *reinterpret_cast<float2*>(ob + col) = v;
        }
    }
}

// ---------------- flash attention: int8 QK^T (2-digit) + bf16 PV --------------
// SMEM: Q s8 [128 rows][hi 256B | lo 256B] @0 (64KB); 4 K/V buffers of 32KB:
//   B0@65536 B1@98304 B2@131072 B3@163840.  K chunk: 128 keys x [hi128B|lo128B].
//   V bf16 overlays: Vh@B0, Vl@B1 ([128 ci][128 keys x 2B] rows).
#define SQ8   0u
#define SB0   65536u
#define SB1   98304u
#define SB2   131072u
#define SB3   163840u
#define FSMEM 196608

// K chunk loader: 128 keys x 128 c, two s8 digit arrays -> 256B rows, 16 units
__device__ __forceinline__ void cp_kchunk(uint32_t sdst, const int8_t* g1, const int8_t* g2) {
    int t = threadIdx.x;
#pragma unroll
    for (int i = 0; i < 8; i++) {
        int e = t + (i << 8);          // 2048 cp16
        int r = e >> 4, u = e & 15;
        uint32_t su = (uint32_t)(u ^ (r & 7));
        const void* src = (u < 8) ? (const void*)(g1 + (size_t)r * Cc + u * 16)
                                  : (const void*)(g2 + (size_t)r * Cc + (u - 8) * 16);
        cp16(sdst + ((uint32_t)r << 8) + (su << 4), src);
    }
}
// V half: 128 ci x 128 keys bf16 (256B rows), gmem row stride NNp
__device__ __forceinline__ void cp_vhalf(uint32_t sdst, const __nv_bfloat16* g) {
    int t = threadIdx.x;
#pragma unroll
    for (int i = 0; i < 8; i++) {
        int e = t + (i << 8);
        int r = e >> 4, u = e & 15;
        uint32_t su = (uint32_t)(u ^ (r & 7));
        cp16(sdst + ((uint32_t)r << 8) + (su << 4), g + (size_t)r * NNp + u * 8);
    }
}

__global__ __launch_bounds__(256, 1) void k_flash_mma() {
    extern __shared__ char sm[];
    uint32_t sb = smem_u32(sm);
    int t = threadIdx.x;
    int L = t & 31;
    int wid = t >> 5;                  // warp owns rows 16*wid .. +15
    int b  = blockIdx.y;
    int m0 = blockIdx.x * 128;

    const int8_t* xq1 = d_xq1 + (size_t)b * NNp * Cc;
    const int8_t* xq2 = d_xq2 + (size_t)b * NNp * Cc;
    const __nv_bfloat16* vh = d_gxh + (size_t)b * CIc * NNp;
    const __nv_bfloat16* vl = d_gxl + (size_t)b * CIc * NNp;

    // scale constants (d_xmax written by k_absmax earlier in stream)
    float um = __uint_as_float(d_xmax);
    float s1 = fmaxf(um * 1.02f, 1e-20f) / 16256.f;
    float s2c = s1 * s1;
    float cA = s2c * 16384.f;
    float cB = s2c * 128.f;

    // ---- prologue: Q (both digits) + chunk0 -> B3 ----
#pragma unroll
    for (int i = 0; i < 16; i++) {
        int e = t + (i << 8);          // 4096 cp16
        int r = e >> 5, u = e & 31;
        uint32_t su = (uint32_t)(u ^ (r & 7));
        const void* src = (u < 16) ? (const void*)(xq1 + (size_t)(m0 + r) * Cc + u * 16)
                                   : (const void*)(xq2 + (size_t)(m0 + r) * Cc + (u - 16) * 16);
        cp16(sb + SQ8 + ((uint32_t)r << 9) + (su << 4), src);
    }
    cp_kchunk(sb + SB3, xq1, xq2);
    cp_commit();

    uint32_t qrow = (uint32_t)(16 * wid + (L & 15));
    uint32_t qsw  = qrow & 7;
    uint32_t qk8  = (uint32_t)(L >> 4);
    uint32_t krow = (uint32_t)((L & 7) + ((L >> 4) << 3));
    uint32_t ksw  = krow & 7;
    uint32_t bk   = (uint32_t)((L >> 3) & 1);

    float Y[16][4];
    float rs0 = 0.f, rs1 = 0.f;
#pragma unroll
    for (int j = 0; j < 16; j++)
#pragma unroll
        for (int q = 0; q < 4; q++) Y[j][q] = 0.f;

    for (int kt = 0; kt < NNp; kt += 128) {
        int accA[16][4], accB[16][4];
#pragma unroll
        for (int j = 0; j < 16; j++)
#pragma unroll
            for (int q = 0; q < 4; q++) { accA[j][q] = 0; accB[j][q] = 0; }

#pragma unroll
        for (int cc = 0; cc < 2; cc++) {
            cp_wait0();
            __syncthreads();
            if (cc == 0) {
                // issue chunk1 -> B2
                cp_kchunk(sb + SB2, xq1 + (size_t)kt * Cc + 128, xq2 + (size_t)kt * Cc + 128);
                cp_commit();
            } else {
                // issue V -> B0/B1
                cp_vhalf(sb + SB0, vh + kt);
                cp_vhalf(sb + SB1, vl + kt);
                cp_commit();
            }
            uint32_t kb = sb + (cc == 0 ? SB3 : SB2);
#pragma unroll
            for (int ks = 0; ks < 4; ks++) {
                int s = cc * 4 + ks;                    // global k32 step 0..7
                uint32_t ah[4], al[4], bh[8][4];
                uint32_t qa = sb + SQ8 + (qrow << 9) +
                              ((((uint32_t)(2 * s) + qk8) ^ qsw) << 4);
                uint32_t ql = sb + SQ8 + (qrow << 9) +
                              ((((uint32_t)(16 + 2 * s) + qk8) ^ qsw) << 4);
                ldsm4(ah, qa);
                ldsm4(al, ql);
                uint32_t uh = (uint32_t)(2 * ks) + bk;
#pragma unroll
                for (int jj = 0; jj < 8; jj++)
                    ldsm4(bh[jj], kb + (((uint32_t)(16 * jj) + krow) << 8) + ((uh ^ ksw) << 4));
#pragma unroll
                for (int j = 0; j < 16; j++) mma_s8(accA[j], ah, &bh[j >> 1][(j & 1) * 2]);
#pragma unroll
                for (int j = 0; j < 16; j++) mma_s8(accB[j], al, &bh[j >> 1][(j & 1) * 2]);
                uint32_t bl[8][4];
#pragma unroll
                for (int jj = 0; jj < 8; jj++)
                    ldsm4(bl[jj], kb + (((uint32_t)(16 * jj) + krow) << 8) + (((uh + 8u) ^ ksw) << 4));
#pragma unroll
                for (int j = 0; j < 16; j++) mma_s8(accB[j], ah, &bl[j >> 1][(j & 1) * 2]);
            }
        }

        // ---- wait V, prefetch next chunk0 -> B3 ----
        cp_wait0();
        __syncthreads();
        int kt2 = (kt + 128) & (NNp - 1);
        cp_kchunk(sb + SB3, xq1 + (size_t)kt2 * Cc, xq2 + (size_t)kt2 * Cc);
        cp_commit();

        // ---- PV with exp from int accumulators, fused per-ks ----
#pragma unroll
        for (int ks = 0; ks < 8; ks++) {
            float e00 = __expf(fmaf(__int2float_rn(accA[2 * ks][0]), cA,
                                    __int2float_rn(accB[2 * ks][0]) * cB));
            float e01 = __expf(fmaf(__int2float_rn(accA[2 * ks][1]), cA,
                                    __int2float_rn(accB[2 * ks][1]) * cB));
            float e02 = __expf(fmaf(__int2float_rn(accA[2 * ks][2]), cA,
                                    __int2float_rn(accB[2 * ks][2]) * cB));
            float e03 = __expf(fmaf(__int2float_rn(accA[2 * ks][3]), cA,
                                    __int2float_rn(accB[2 * ks][3]) * cB));
            float e10 = __expf(fmaf(__int2float_rn(accA[2 * ks + 1][0]), cA,
                                    __int2float_rn(accB[2 * ks + 1][0]) * cB));
            float e11 = __expf(fmaf(__int2float_rn(accA[2 * ks + 1][1]), cA,
                                    __int2float_rn(accB[2 * ks + 1][1]) * cB));
            float e12 = __expf(fmaf(__int2float_rn(accA[2 * ks + 1][2]), cA,
                                    __int2float_rn(accB[2 * ks + 1][2]) * cB));
            float e13 = __expf(fmaf(__int2float_rn(accA[2 * ks + 1][3]), cA,
                                    __int2float_rn(accB[2 * ks + 1][3]) * cB));
            rs0 += e00 + e01 + e10 + e11;
            rs1 += e02 + e03 + e12 + e13;
            uint32_t PH[4], PL[4];
            split2(e00, e01, PH[0], PL[0]);
            split2(e02, e03, PH[1], PL[1]);
            split2(e10, e11, PH[2], PL[2]);
            split2(e12, e13, PH[3], PL[3]);

            uint32_t bv[8][4];
            uint32_t vsw = ((((uint32_t)(ks * 2) + bk) ^ ksw) << 4);
#pragma unroll
            for (int jj = 0; jj < 8; jj++)
                ldsm4(bv[jj], sb + SB0 + (((uint32_t)(16 * jj) + krow) << 8) + vsw);
#pragma unroll
            for (int j = 0; j < 16; j++) mma_bf16(Y[j], PH, &bv[j >> 1][(j & 1) * 2]);
#pragma unroll
            for (int j = 0; j < 16; j++) mma_bf16(Y[j], PL, &bv[j >> 1][(j & 1) * 2]);
#pragma unroll
            for (int jj = 0; jj < 8; jj++)
                ldsm4(bv[jj], sb + SB1 + (((uint32_t)(16 * jj) + krow) << 8) + vsw);
#pragma unroll
            for (int j = 0; j < 16; j++) mma_bf16(Y[j], PH, &bv[j >> 1][(j & 1) * 2]);
        }
    }

    // ---- epilogue: rowsums within warp; split-bf16 store of y ----
    rs0 += __shfl_xor_sync(0xffffffffu, rs0, 1);
    rs0 += __shfl_xor_sync(0xffffffffu, rs0, 2);
    rs1 += __shfl_xor_sync(0xffffffffu, rs1, 1);
    rs1 += __shfl_xor_sync(0xffffffffu, rs1, 2);
    float inv0 = 1.f / rs0;
    float inv1 = 1.f / rs1;

    int r0 = 16 * wid + (L >> 2);
    __nv_bfloat16* yh0 = d_yh + ((size_t)b * NNp + m0 + r0) * CIc;
    __nv_bfloat16* yl0 = d_yl + ((size_t)b * NNp + m0 + r0) * CIc;
#pragma unroll
    for (int j = 0; j < 16; j++) {
        int col = 8 * j + 2 * (L & 3);
        uint32_t h, l;
        split2(Y[j][0] * inv0, Y[j][1] * inv0, h, l);
        *reinterpret_cast<uint32_t*>(yh0 + col) = h;
        *reinterpret_cast<uint32_t*>(yl0 + col) = l;
        split2(Y[j][2] * inv1, Y[j][3] * inv1, h, l);
        *reinterpret_cast<uint32_t*>(yh0 + 8 * CIc + col) = h;
        *reinterpret_cast<uint32_t*>(yl0 + 8 * CIc + col) = l;
    }
}

// ---------------- BN stats (single stage, deterministic) -----------------------
__global__ void k_bnstats2() {
    __shared__ float sS[256], sQ[256];
    int c = blockIdx.x, t = threadIdx.x;
    float s = 0.f, q = 0.f;
#pragma unroll
    for (int b = 0; b < Bq; b++) {
        const float* p = d_wy + ((size_t)b * Cc + c) * NNp;
#pragma unroll
        for (int i = 0; i < 16; i++) {
            float v = p[t + (i << 8)];
            s += v; q += v * v;
        }
    }
    sS[t] = s; sQ[t] = q;
    __syncthreads();
#pragma unroll
    for (int o = 128; o > 0; o >>= 1) {
        if (t < o) { sS[t] += sS[t + o]; sQ[t] += sQ[t + o]; }
        __syncthreads();
    }
    if (t == 0) { d_sum[c] = sS[0]; d_sqs[c] = sQ[0]; }
}

// ---------------- BN apply + residual (elementwise; wy already [c][n]) --------
__global__ void k_bnfinal2(const float* __restrict__ x,
                           const float* __restrict__ gamma,
                           const float* __restrict__ beta,
                           float* __restrict__ out) {
    size_t base = ((size_t)blockIdx.x * 256 + threadIdx.x) * 4;
    int c = (int)((base >> 12) & 255);
    const float invn = 1.f / (float)(Bq * NNp);
    float mean = d_sum[c] * invn;
    float var  = d_sqs[c] * invn - mean * mean;
    float rsv  = rsqrtf(var + EPSc);
    float g    = gamma[c] * rsv;
    float be   = beta[c] - mean * g;
    float4 w  = *reinterpret_cast<const float4*>(d_wy + base);
    float4 xv = *reinterpret_cast<const float4*>(x + base);
    float4 o;
    o.x = w.x * g + be + xv.x;
    o.y = w.y * g + be + xv.y;
    o.z = w.z * g + be + xv.z;
    o.w = w.w * g + be + xv.w;
    *reinterpret_cast<float4*>(out + base) = o;
}

// ---------------- launch -------------------------------------------------------
extern "C" void kernel_launch(void* const* d_in, const int* in_sizes, int n_in,
                              void* d_out, int out_size) {
    const float* x     = (const float*)d_in[0];
    const float* g_w   = (const float*)d_in[1];
    const float* g_b   = (const float*)d_in[2];
    const float* W_w   = (const float*)d_in[3];
    const float* W_b   = (const float*)d_in[4];
    const float* gamma = (const float*)d_in[5];
    const float* beta  = (const float*)d_in[6];
    float* out = (float*)d_out;

    (void)in_sizes; (void)n_in; (void)out_size;

    cudaFuncSetAttribute(k_flash_mma, cudaFuncAttributeMaxDynamicSharedMemorySize, FSMEM);
    cudaFuncSetAttribute(k_gx_mma, cudaFuncAttributeMaxDynamicSharedMemorySize, GSMEM);
    cudaFuncSetAttribute(k_wy_mma, cudaFuncAttributeMaxDynamicSharedMemorySize, GSMEM);

    k_reset<<<1, 1>>>();
    k_absmax<<<1024, 256>>>(x);
    k_transpose<<<dim3(NNp / 32, Cc / 32, Bq), dim3(32, 8)>>>(x);
    k_split_w<<<128, 256>>>(g_w, W_w);
    k_gx_mma<<<128, 256, GSMEM>>>(g_b);
    k_flash_mma<<<dim3(NNp / 128, Bq), 256, FSMEM>>>();
    k_wy_mma<<<128, 256, GSMEM>>>(W_b);
    k_bnstats2<<<256, 256>>>();
    k_bnfinal2<<<4096, 256>>>(x, gamma, beta, out);
}

// round 12
// speedup vs baseline: 2.5895x; 2.5895x over previous
#include <cuda_runtime.h>
#include <cuda_bf16.h>
#include <math.h>
#include <stdint.h>
#include <string.h>

#define Bq 4
#define Cc 256
#define CIc 128
#define NNp 4096
#define EPSc 1e-5f

// ---------------- scratch (device globals; no allocations allowed) ------------
__device__ float d_wy[Bq * NNp * Cc];                 // [b][c][n] fp32
__device__ __nv_bfloat16 d_xh [Bq * NNp * Cc];        // [b][n][c] bf16 hi
__device__ __nv_bfloat16 d_xl [Bq * NNp * Cc];        // [b][n][c] bf16 lo
__device__ __nv_bfloat16 d_gxh[Bq * CIc * NNp];       // [b][ci][n] bf16 hi
__device__ __nv_bfloat16 d_gxl[Bq * CIc * NNp];       // [b][ci][n] bf16 lo
__device__ __nv_bfloat16 d_yh [Bq * NNp * CIc];       // [b][n][ci] bf16 hi
__device__ __nv_bfloat16 d_yl [Bq * NNp * CIc];       // [b][n][ci] bf16 lo
__device__ __nv_bfloat16 d_gwh[CIc * Cc], d_gwl[CIc * Cc];
__device__ __nv_bfloat16 d_Wwh[Cc * CIc], d_Wwl[Cc * CIc];
__device__ float d_psum[128 * Cc];                    // per-wy-block partial sums
__device__ float d_psq [128 * Cc];
__device__ float d_sum[Cc];
__device__ float d_sqs[Cc];

// ---------------- helpers ------------------------------------------------------
__device__ __forceinline__ uint32_t smem_u32(const void* p) {
    uint32_t a;
    asm("{ .reg .u64 t; cvta.to.shared.u64 t, %1; cvt.u32.u64 %0, t; }"
        : "=r"(a) : "l"(p));
    return a;
}
__device__ __forceinline__ void ldsm4(uint32_t* r, uint32_t addr) {
    asm volatile("ldmatrix.sync.aligned.m8n8.x4.shared.b16 {%0,%1,%2,%3}, [%4];"
                 : "=r"(r[0]), "=r"(r[1]), "=r"(r[2]), "=r"(r[3]) : "r"(addr));
}
__device__ __forceinline__ void mma_bf16(float* c, const uint32_t* a, const uint32_t* b) {
    asm volatile("mma.sync.aligned.m16n8k16.row.col.f32.bf16.bf16.f32 "
                 "{%0,%1,%2,%3}, {%4,%5,%6,%7}, {%8,%9}, {%0,%1,%2,%3};"
                 : "+f"(c[0]), "+f"(c[1]), "+f"(c[2]), "+f"(c[3])
                 : "r"(a[0]), "r"(a[1]), "r"(a[2]), "r"(a[3]), "r"(b[0]), "r"(b[1]));
}
__device__ __forceinline__ void cp16(uint32_t s, const void* g) {
    asm volatile("cp.async.cg.shared.global [%0], [%1], 16;" :: "r"(s), "l"(g) : "memory");
}
__device__ __forceinline__ void cp_commit() {
    asm volatile("cp.async.commit_group;" ::: "memory");
}
__device__ __forceinline__ void cp_wait0() {
    asm volatile("cp.async.wait_group 0;" ::: "memory");
}
// pack(x->low, y->high) bf16x2, plus residual pack
__device__ __forceinline__ void split2(float x, float y, uint32_t& h, uint32_t& l) {
    __nv_bfloat16 xh = __float2bfloat16(x);
    __nv_bfloat16 yh = __float2bfloat16(y);
    __nv_bfloat162 hp; hp.x = xh; hp.y = yh;
    h = *reinterpret_cast<uint32_t*>(&hp);
    float xr = x - __bfloat162float(xh);
    float yr = y - __bfloat162float(yh);
    __nv_bfloat162 lp = __floats2bfloat162_rn(xr, yr);
    l = *reinterpret_cast<uint32_t*>(&lp);
}

// generic [128 rows][64 col] bf16 chunk loader, XOR-swizzled, gmem row stride gs
__device__ __forceinline__ void cp_chunkS(uint32_t sdst, const __nv_bfloat16* g, int gs) {
    int t = threadIdx.x;
#pragma unroll
    for (int i = 0; i < 4; i++) {
        int e = t + (i << 8);
        int r = e >> 3, u = e & 7;
        uint32_t su = (uint32_t)(u ^ (r & 7));
        cp16(sdst + ((uint32_t)r << 7) + (su << 4), g + (size_t)r * gs + u * 8);
    }
}

// ---------------- transpose x[b][c][n] -> xh/xl[b][n][c] ----------------------
__global__ void k_transpose(const float* __restrict__ x) {
    __shared__ float tile[32][33];
    int b  = blockIdx.z;
    int n0 = blockIdx.x * 32;
    int c0 = blockIdx.y * 32;
    int tx = threadIdx.x, ty = threadIdx.y;            // 32 x 8
    const float* xb = x + (size_t)b * Cc * NNp;
#pragma unroll
    for (int j = 0; j < 4; j++) {
        int c = c0 + ty + 8 * j;
        tile[ty + 8 * j][tx] = xb[(size_t)c * NNp + n0 + tx];
    }
    __syncthreads();
    __nv_bfloat16* xhb = d_xh + (size_t)b * NNp * Cc;
    __nv_bfloat16* xlb = d_xl + (size_t)b * NNp * Cc;
#pragma unroll
    for (int j = 0; j < 4; j++) {
        int n = n0 + ty + 8 * j;
        float v = tile[tx][ty + 8 * j];
        size_t o = (size_t)n * Cc + c0 + tx;
        __nv_bfloat16 h = __float2bfloat16(v);
        xhb[o] = h;
        xlb[o] = __float2bfloat16(v - __bfloat162float(h));
    }
}

// ---------------- weight splits ------------------------------------------------
__global__ void k_split_w(const float* __restrict__ gw, const float* __restrict__ Ww) {
    int i = blockIdx.x * 256 + threadIdx.x;        // 128 blocks x 256 = 32768
    float v = gw[i];
    __nv_bfloat16 h = __float2bfloat16(v);
    d_gwh[i] = h; d_gwl[i] = __float2bfloat16(v - __bfloat162float(h));
    v = Ww[i];
    h = __float2bfloat16(v);
    d_Wwh[i] = h; d_Wwl[i] = __float2bfloat16(v - __bfloat162float(h));
}

// ---------------- gxT[b][ci][n] = g_w x + g_b  (split-bf16 mma) ---------------
// A = g_w [128 ci][256 c] resident; B = xh/xl [n][c] chunks; C rows=ci, cols=n.
#define GXA_H 0u
#define GXA_L 65536u
#define GXB0  131072u
#define GSMEM 196608

__global__ __launch_bounds__(256, 1) void k_gx_mma(const float* __restrict__ gb) {
    extern __shared__ char sm[];
    uint32_t sb = smem_u32(sm);
    int t = threadIdx.x, L = t & 31, wid = t >> 5;
    int bx = blockIdx.x;
    int b  = bx >> 5;
    int n0 = (bx & 31) << 7;
    const __nv_bfloat16* Bh = d_xh + ((size_t)b * NNp + n0) * Cc;
    const __nv_bfloat16* Bl = d_xl + ((size_t)b * NNp + n0) * Cc;

    // A: 128 rows x 32 units (512B rows)
#pragma unroll
    for (int i = 0; i < 16; i++) {
        int e = t + (i << 8);
        int r = e >> 5, u = e & 31;
        uint32_t su = (uint32_t)(u ^ (r & 7));
        cp16(sb + GXA_H + ((uint32_t)r << 9) + (su << 4), d_gwh + (size_t)r * Cc + u * 8);
        cp16(sb + GXA_L + ((uint32_t)r << 9) + (su << 4), d_gwl + (size_t)r * Cc + u * 8);
    }
    cp_chunkS(sb + GXB0, Bh, Cc);
    cp_chunkS(sb + GXB0 + 16384u, Bl, Cc);
    cp_commit();

    uint32_t qrow = (uint32_t)(16 * wid + (L & 15));
    uint32_t qsw  = qrow & 7;
    uint32_t qk8  = (uint32_t)(L >> 4);
    uint32_t krow = (uint32_t)((L & 7) + ((L >> 4) << 3));
    uint32_t ksw  = krow & 7;
    uint32_t bk   = (uint32_t)((L >> 3) & 1);

    float acc[16][4];
#pragma unroll
    for (int j = 0; j < 16; j++)
#pragma unroll
        for (int q = 0; q < 4; q++) acc[j][q] = 0.f;

    for (int kc = 0; kc < 4; kc++) {
        cp_wait0();
        __syncthreads();
        if (kc < 3) {
            uint32_t nb = GXB0 + ((uint32_t)((kc + 1) & 1)) * 32768u;
            cp_chunkS(sb + nb, Bh + (kc + 1) * 64, Cc);
            cp_chunkS(sb + nb + 16384u, Bl + (kc + 1) * 64, Cc);
            cp_commit();
        }
        uint32_t bbh = sb + GXB0 + ((uint32_t)(kc & 1)) * 32768u;
        uint32_t bbl = bbh + 16384u;
#pragma unroll
        for (int ks = 0; ks < 4; ks++) {
            uint32_t ah[4], al[4], br[8][4];
            uint32_t ku = (uint32_t)(kc * 8 + ks * 2) + qk8;
            uint32_t qa = sb + GXA_H + (qrow << 9) + ((ku ^ qsw) << 4);
            ldsm4(ah, qa);
            ldsm4(al, qa + 65536u);
            uint32_t bsw = (((uint32_t)(ks * 2) + bk) ^ ksw) << 4;
#pragma unroll
            for (int jj = 0; jj < 8; jj++)
                ldsm4(br[jj], bbh + (((uint32_t)(16 * jj) + krow) << 7) + bsw);
#pragma unroll
            for (int j = 0; j < 16; j++) mma_bf16(acc[j], ah, &br[j >> 1][(j & 1) * 2]);
#pragma unroll
            for (int j = 0; j < 16; j++) mma_bf16(acc[j], al, &br[j >> 1][(j & 1) * 2]);
#pragma unroll
            for (int jj = 0; jj < 8; jj++)
                ldsm4(br[jj], bbl + (((uint32_t)(16 * jj) + krow) << 7) + bsw);
#pragma unroll
            for (int j = 0; j < 16; j++) mma_bf16(acc[j], ah, &br[j >> 1][(j & 1) * 2]);
        }
    }

    int ci0 = 16 * wid + (L >> 2);
    float b0 = gb[ci0], b1 = gb[ci0 + 8];
    __nv_bfloat16* oh = d_gxh + ((size_t)b * CIc + ci0) * NNp + n0;
    __nv_bfloat16* ol = d_gxl + ((size_t)b * CIc + ci0) * NNp + n0;
#pragma unroll
    for (int j = 0; j < 16; j++) {
        int col = 8 * j + 2 * (L & 3);
        uint32_t h, l;
        split2(acc[j][0] + b0, acc[j][1] + b0, h, l);
        *reinterpret_cast<uint32_t*>(oh + col) = h;
        *reinterpret_cast<uint32_t*>(ol + col) = l;
        split2(acc[j][2] + b1, acc[j][3] + b1, h, l);
        *reinterpret_cast<uint32_t*>(oh + 8 * NNp + col) = h;
        *reinterpret_cast<uint32_t*>(ol + 8 * NNp + col) = l;
    }
}

// ---------------- wy[b][c][n] = W_w y + W_b  (split-bf16 mma) + BN partials ---
// A = W_w [256 c][128 ci] resident; B = yh/yl [n][ci] chunks; C rows=c, cols=n.
__global__ __launch_bounds__(256, 1) void k_wy_mma(const float* __restrict__ Wb) {
    extern __shared__ char sm[];
    uint32_t sb = smem_u32(sm);
    int t = threadIdx.x, L = t & 31, wid = t >> 5;
    int bx = blockIdx.x;
    int b  = bx >> 5;
    int n0 = (bx & 31) << 7;
    const __nv_bfloat16* Bh = d_yh + ((size_t)b * NNp + n0) * CIc;
    const __nv_bfloat16* Bl = d_yl + ((size_t)b * NNp + n0) * CIc;

    // A: 256 rows x 16 units (256B rows)
#pragma unroll
    for (int i = 0; i < 16; i++) {
        int e = t + (i << 8);
        int r = e >> 4, u = e & 15;
        uint32_t su = (uint32_t)(u ^ (r & 7));
        cp16(sb + GXA_H + ((uint32_t)r << 8) + (su << 4), d_Wwh + (size_t)r * CIc + u * 8);
        cp16(sb + GXA_L + ((uint32_t)r << 8) + (su << 4), d_Wwl + (size_t)r * CIc + u * 8);
    }
    cp_chunkS(sb + GXB0, Bh, CIc);
    cp_chunkS(sb + GXB0 + 16384u, Bl, CIc);
    cp_commit();

    uint32_t arow0 = (uint32_t)(32 * wid + (L & 15));
    uint32_t qk8   = (uint32_t)(L >> 4);
    uint32_t krow  = (uint32_t)((L & 7) + ((L >> 4) << 3));
    uint32_t ksw   = krow & 7;
    uint32_t bk    = (uint32_t)((L >> 3) & 1);

    float acc[2][16][4];
#pragma unroll
    for (int mt = 0; mt < 2; mt++)
#pragma unroll
        for (int j = 0; j < 16; j++)
#pragma unroll
            for (int q = 0; q < 4; q++) acc[mt][j][q] = 0.f;

    for (int kc = 0; kc < 2; kc++) {
        cp_wait0();
        __syncthreads();
        if (kc < 1) {
            cp_chunkS(sb + GXB0 + 32768u, Bh + 64, CIc);
            cp_chunkS(sb + GXB0 + 49152u, Bl + 64, CIc);
            cp_commit();
        }
        uint32_t bbh = sb + GXB0 + ((uint32_t)kc) * 32768u;
        uint32_t bbl = bbh + 16384u;
#pragma unroll
        for (int ks = 0; ks < 4; ks++) {
            uint32_t ah[2][4], al[2][4], br[8][4];
            uint32_t ku = (uint32_t)(kc * 8 + ks * 2) + qk8;
#pragma unroll
            for (int mt = 0; mt < 2; mt++) {
                uint32_t ar = arow0 + 16u * (uint32_t)mt;
                uint32_t qa = sb + GXA_H + (ar << 8) + ((ku ^ (ar & 7)) << 4);
                ldsm4(ah[mt], qa);
                ldsm4(al[mt], qa + 65536u);
            }
            uint32_t bsw = (((uint32_t)(ks * 2) + bk) ^ ksw) << 4;
#pragma unroll
            for (int jj = 0; jj < 8; jj++)
                ldsm4(br[jj], bbh + (((uint32_t)(16 * jj) + krow) << 7) + bsw);
#pragma unroll
            for (int mt = 0; mt < 2; mt++)
#pragma unroll
                for (int j = 0; j < 16; j++)
                    mma_bf16(acc[mt][j], ah[mt], &br[j >> 1][(j & 1) * 2]);
#pragma unroll
            for (int mt = 0; mt < 2; mt++)
#pragma unroll
                for (int j = 0; j < 16; j++)
                    mma_bf16(acc[mt][j], al[mt], &br[j >> 1][(j & 1) * 2]);
#pragma unroll
            for (int jj = 0; jj < 8; jj++)
                ldsm4(br[jj], bbl + (((uint32_t)(16 * jj) + krow) << 7) + bsw);
#pragma unroll
            for (int mt = 0; mt < 2; mt++)
#pragma unroll
                for (int j = 0; j < 16; j++)
                    mma_bf16(acc[mt][j], ah[mt], &br[j >> 1][(j & 1) * 2]);
        }
    }

    int c0 = 32 * wid + (L >> 2);
    float ps[4], pq[4];                 // BN partials: [mt][qh]
#pragma unroll
    for (int i = 0; i < 4; i++) { ps[i] = 0.f; pq[i] = 0.f; }

#pragma unroll
    for (int mt = 0; mt < 2; mt++) {
        int ca = c0 + 16 * mt, cb = ca + 8;
        float ba = Wb[ca], bb2 = Wb[cb];
        float* oa = d_wy + ((size_t)b * Cc + ca) * NNp + n0;
        float* ob = d_wy + ((size_t)b * Cc + cb) * NNp + n0;
#pragma unroll
        for (int j = 0; j < 16; j++) {
            int col = 8 * j + 2 * (L & 3);
            float v0 = acc[mt][j][0] + ba;
            float v1 = acc[mt][j][1] + ba;
            float v2 = acc[mt][j][2] + bb2;
            float v3 = acc[mt][j][3] + bb2;
            float2 w;
            w.x = v0; w.y = v1;
            *reinterpret_cast<float2*>(oa + col) = w;
            w.x = v2; w.y = v3;
            *reinterpret_cast<float2*>(ob + col) = w;
            ps[mt * 2]     += v0 + v1;
            pq[mt * 2]     += v0 * v0 + v1 * v1;
            ps[mt * 2 + 1] += v2 + v3;
            pq[mt * 2 + 1] += v2 * v2 + v3 * v3;
        }
    }
    // reduce over the 4 lanes sharing each channel (bits 0-1 of L)
#pragma unroll
    for (int i = 0; i < 4; i++) {
        ps[i] += __shfl_xor_sync(0xffffffffu, ps[i], 1);
        ps[i] += __shfl_xor_sync(0xffffffffu, ps[i], 2);
        pq[i] += __shfl_xor_sync(0xffffffffu, pq[i], 1);
        pq[i] += __shfl_xor_sync(0xffffffffu, pq[i], 2);
    }
    if ((L & 3) == 0) {
#pragma unroll
        for (int mt = 0; mt < 2; mt++) {
#pragma unroll
            for (int qh = 0; qh < 2; qh++) {
                int c = c0 + 16 * mt + 8 * qh;
                d_psum[bx * Cc + c] = ps[mt * 2 + qh];
                d_psq [bx * Cc + c] = pq[mt * 2 + qh];
            }
        }
    }
}

// ---------------- flash attention via mma.sync (split-bf16, no-max softmax) ---
#define SQH   0u
#define SQL   65536u
#define KB0H  131072u
#define KB0L  147456u
#define KB1H  163840u
#define KB1L  180224u
#define KB2H  196608u
#define KB2L  212992u
#define SVH   131072u
#define SVL   163840u
#define FSMEM 229376

__device__ __forceinline__ void cp_chunk(uint32_t sdst, const __nv_bfloat16* g) {
    cp_chunkS(sdst, g, Cc);
}
__device__ __forceinline__ void cp_vhalf(uint32_t sdst, const __nv_bfloat16* g) {
    int t = threadIdx.x;
#pragma unroll
    for (int i = 0; i < 8; i++) {
        int e = t + (i << 8);
        int r = e >> 4, u = e & 15;
        uint32_t su = (uint32_t)(u ^ (r & 7));
        cp16(sdst + ((uint32_t)r << 8) + (su << 4), g + (size_t)r * NNp + u * 8);
    }
}

__global__ __launch_bounds__(256, 1) void k_flash_mma() {
    extern __shared__ char sm[];
    uint32_t sb = smem_u32(sm);
    int t = threadIdx.x;
    int L = t & 31;
    int wid = t >> 5;                  // warp owns rows 16*wid .. +15
    int b  = blockIdx.y;
    int m0 = blockIdx.x * 128;

    const __nv_bfloat16* xh = d_xh + (size_t)b * NNp * Cc;
    const __nv_bfloat16* xl = d_xl + (size_t)b * NNp * Cc;
    const __nv_bfloat16* vh = d_gxh + (size_t)b * CIc * NNp;
    const __nv_bfloat16* vl = d_gxl + (size_t)b * CIc * NNp;

#pragma unroll
    for (int i = 0; i < 16; i++) {
        int e = t + (i << 8);
        int r = e >> 5, u = e & 31;
        uint32_t su = (uint32_t)(u ^ (r & 7));
        cp16(sb + SQH + ((uint32_t)r << 9) + (su << 4), xh + (size_t)(m0 + r) * Cc + u * 8);
        cp16(sb + SQL + ((uint32_t)r << 9) + (su << 4), xl + (size_t)(m0 + r) * Cc + u * 8);
    }
    cp_chunk(sb + KB2H, xh);
    cp_chunk(sb + KB2L, xl);
    cp_commit();

    uint32_t qrow = (uint32_t)(16 * wid + (L & 15));
    uint32_t qsw  = qrow & 7;
    uint32_t qk8  = (uint32_t)(L >> 4);
    uint32_t krow = (uint32_t)((L & 7) + ((L >> 4) << 3));
    uint32_t ksw  = krow & 7;
    uint32_t bk   = (uint32_t)((L >> 3) & 1);

    float Y[16][4];
    float rs0 = 0.f, rs1 = 0.f;
#pragma unroll
    for (int j = 0; j < 16; j++)
#pragma unroll
        for (int q = 0; q < 4; q++) Y[j][q] = 0.f;

    const uint32_t rdH[4] = {KB2H, KB0H, KB1H, KB2H};
    const uint32_t rdL[4] = {KB2L, KB0L, KB1L, KB2L};

    for (int kt = 0; kt < NNp; kt += 128) {
        float S[16][4];
#pragma unroll
        for (int j = 0; j < 16; j++)
#pragma unroll
            for (int q = 0; q < 4; q++) S[j][q] = 0.f;

#pragma unroll
        for (int cc = 0; cc < 4; cc++) {
            cp_wait0();
            __syncthreads();
            if (cc == 0) {
                cp_chunk(sb + KB0H, xh + (size_t)kt * Cc + 64);
                cp_chunk(sb + KB0L, xl + (size_t)kt * Cc + 64);
                cp_commit();
            } else if (cc == 1) {
                cp_chunk(sb + KB1H, xh + (size_t)kt * Cc + 128);
                cp_chunk(sb + KB1L, xl + (size_t)kt * Cc + 128);
                cp_commit();
            } else if (cc == 2) {
                cp_chunk(sb + KB2H, xh + (size_t)kt * Cc + 192);
                cp_chunk(sb + KB2L, xl + (size_t)kt * Cc + 192);
                cp_commit();
            } else {
                cp_vhalf(sb + SVH, vh + kt);
                cp_vhalf(sb + SVL, vl + kt);
                cp_commit();
            }
            uint32_t kbh = sb + rdH[cc], kbl = sb + rdL[cc];
#pragma unroll
            for (int ks = 0; ks < 4; ks++) {
                uint32_t ah[4], al[4], br[8][4];
                uint32_t qunit = (uint32_t)(cc * 8 + ks * 2) + qk8;
                uint32_t qa = sb + SQH + (qrow << 9) + (((qunit ^ qsw)) << 4);
                ldsm4(ah, qa);
                ldsm4(al, qa + SQL);
                uint32_t bsw = ((((uint32_t)(ks * 2) + bk) ^ ksw) << 4);
#pragma unroll
                for (int jj = 0; jj < 8; jj++)
                    ldsm4(br[jj], kbh + (((uint32_t)(16 * jj) + krow) << 7) + bsw);
#pragma unroll
                for (int j = 0; j < 16; j++) mma_bf16(S[j], ah, &br[j >> 1][(j & 1) * 2]);
#pragma unroll
                for (int j = 0; j < 16; j++) mma_bf16(S[j], al, &br[j >> 1][(j & 1) * 2]);
#pragma unroll
                for (int jj = 0; jj < 8; jj++)
                    ldsm4(br[jj], kbl + (((uint32_t)(16 * jj) + krow) << 7) + bsw);
#pragma unroll
                for (int j = 0; j < 16; j++) mma_bf16(S[j], ah, &br[j >> 1][(j & 1) * 2]);
            }
        }

        // ---- wait V (issued a full chunk ago; already resident), prefetch next ----
        cp_wait0();
        __syncthreads();
        int kt2 = (kt + 128) & (NNp - 1);
        cp_chunk(sb + KB2H, xh + (size_t)kt2 * Cc);
        cp_chunk(sb + KB2L, xl + (size_t)kt2 * Cc);
        cp_commit();

        // ---- PV with exp/split fused per-ks ----
#pragma unroll
        for (int ks = 0; ks < 8; ks++) {
            float e00 = __expf(S[2 * ks][0]);
            float e01 = __expf(S[2 * ks][1]);
            float e02 = __expf(S[2 * ks][2]);
            float e03 = __expf(S[2 * ks][3]);
            float e10 = __expf(S[2 * ks + 1][0]);
            float e11 = __expf(S[2 * ks + 1][1]);
            float e12 = __expf(S[2 * ks + 1][2]);
            float e13 = __expf(S[2 * ks + 1][3]);
            rs0 += e00 + e01 + e10 + e11;
            rs1 += e02 + e03 + e12 + e13;
            uint32_t PH[4], PL[4];
            split2(e00, e01, PH[0], PL[0]);
            split2(e02, e03, PH[1], PL[1]);
            split2(e10, e11, PH[2], PL[2]);
            split2(e12, e13, PH[3], PL[3]);

            uint32_t bv[8][4];
            uint32_t vsw = ((((uint32_t)(ks * 2) + bk) ^ ksw) << 4);
#pragma unroll
            for (int jj = 0; jj < 8; jj++)
                ldsm4(bv[jj], sb + SVH + (((uint32_t)(16 * jj) + krow) << 8) + vsw);
#pragma unroll
            for (int j = 0; j < 16; j++) mma_bf16(Y[j], PH, &bv[j >> 1][(j & 1) * 2]);
#pragma unroll
            for (int j = 0; j < 16; j++) mma_bf16(Y[j], PL, &bv[j >> 1][(j & 1) * 2]);
#pragma unroll
            for (int jj = 0; jj < 8; jj++)
                ldsm4(bv[jj], sb + SVL + (((uint32_t)(16 * jj) + krow) << 8) + vsw);
#pragma unroll
            for (int j = 0; j < 16; j++) mma_bf16(Y[j], PH, &bv[j >> 1][(j & 1) * 2]);
        }
    }

    // ---- epilogue: rowsums within warp; split-bf16 store of y ----
    rs0 += __shfl_xor_sync(0xffffffffu, rs0, 1);
    rs0 += __shfl_xor_sync(0xffffffffu, rs0, 2);
    rs1 += __shfl_xor_sync(0xffffffffu, rs1, 1);
    rs1 += __shfl_xor_sync(0xffffffffu, rs1, 2);
    float inv0 = 1.f / rs0;
    float inv1 = 1.f / rs1;

    int r0 = 16 * wid + (L >> 2);
    __nv_bfloat16* yh0 = d_yh + ((size_t)b * NNp + m0 + r0) * CIc;
    __nv_bfloat16* yl0 = d_yl + ((size_t)b * NNp + m0 + r0) * CIc;
#pragma unroll
    for (int j = 0; j < 16; j++) {
        int col = 8 * j + 2 * (L & 3);
        uint32_t h, l;
        split2(Y[j][0] * inv0, Y[j][1] * inv0, h, l);
        *reinterpret_cast<uint32_t*>(yh0 + col) = h;
        *reinterpret_cast<uint32_t*>(yl0 + col) = l;
        split2(Y[j][2] * inv1, Y[j][3] * inv1, h, l);
        *reinterpret_cast<uint32_t*>(yh0 + 8 * CIc + col) = h;
        *reinterpret_cast<uint32_t*>(yl0 + 8 * CIc + col) = l;
    }
}

// ---------------- BN reduce over 128 per-block partials -------------------------
__global__ void k_bnreduce() {
    int c = threadIdx.x;               // 256 threads, 1 block
    float s = 0.f, q = 0.f;
#pragma unroll 8
    for (int bkx = 0; bkx < 128; bkx++) {
        s += d_psum[bkx * Cc + c];
        q += d_psq [bkx * Cc + c];
    }
    d_sum[c] = s;
    d_sqs[c] = q;
}

// ---------------- BN apply + residual (elementwise; wy already [c][n]) --------
__global__ void k_bnfinal2(const float* __restrict__ x,
                           const float* __restrict__ gamma,
                           const float* __restrict__ beta,
                           float* __restrict__ out) {
    size_t base = ((size_t)blockIdx.x * 256 + threadIdx.x) * 4;
    int c = (int)((base >> 12) & 255);
    const float invn = 1.f / (float)(Bq * NNp);
    float mean = d_sum[c] * invn;
    float var  = d_sqs[c] * invn - mean * mean;
    float rsv  = rsqrtf(var + EPSc);
    float g    = gamma[c] * rsv;
    float be   = beta[c] - mean * g;
    float4 w  = *reinterpret_cast<const float4*>(d_wy + base);
    float4 xv = *reinterpret_cast<const float4*>(x + base);
    float4 o;
    o.x = w.x * g + be + xv.x;
    o.y = w.y * g + be + xv.y;
    o.z = w.z * g + be + xv.z;
    o.w = w.w * g + be + xv.w;
    *reinterpret_cast<float4*>(out + base) = o;
}

// ---------------- launch -------------------------------------------------------
extern "C" void kernel_launch(void* const* d_in, const int* in_sizes, int n_in,
                              void* d_out, int out_size) {
    const float* x     = (const float*)d_in[0];
    const float* g_w   = (const float*)d_in[1];
    const float* g_b   = (const float*)d_in[2];
    const float* W_w   = (const float*)d_in[3];
    const float* W_b   = (const float*)d_in[4];
    const float* gamma = (const float*)d_in[5];
    const float* beta  = (const float*)d_in[6];
    float* out = (float*)d_out;

    (void)in_sizes; (void)n_in; (void)out_size;

    cudaFuncSetAttribute(k_flash_mma, cudaFuncAttributeMaxDynamicSharedMemorySize, FSMEM);
    cudaFuncSetAttribute(k_gx_mma, cudaFuncAttributeMaxDynamicSharedMemorySize, GSMEM);
    cudaFuncSetAttribute(k_wy_mma, cudaFuncAttributeMaxDynamicSharedMemorySize, GSMEM);

    k_transpose<<<dim3(NNp / 32, Cc / 32, Bq), dim3(32, 8)>>>(x);
    k_split_w<<<128, 256>>>(g_w, W_w);
    k_gx_mma<<<128, 256, GSMEM>>>(g_b);
    k_flash_mma<<<dim3(NNp / 128, Bq), 256, FSMEM>>>();
    k_wy_mma<<<128, 256, GSMEM>>>(W_b);
    k_bnreduce<<<1, 256>>>();
    // Bq*Cc*NNp = 4,194,304 floats / (256 thr * 4 per thr) = 4096 blocks
    k_bnfinal2<<<4096, 256>>>(x, gamma, beta, out);
}

// round 13
// speedup vs baseline: 3.6161x; 1.3965x over previous
#include <cuda_runtime.h>
#include <cuda_fp16.h>
#include <math.h>
#include <stdint.h>
#include <string.h>

#define Bq 4
#define Cc 256
#define CIc 128
#define NNp 4096
#define EPSc 1e-5f

// ---------------- scratch (device globals; no allocations allowed) ------------
__device__ float d_wy[Bq * NNp * Cc];                 // [b][c][n] fp32
__device__ __half d_xfh[Bq * NNp * Cc];               // [b][n][c] fp16 hi
__device__ __half d_xfl[Bq * NNp * Cc];               // [b][n][c] fp16 lo
__device__ __half d_gxf[Bq * CIc * NNp];              // [b][ci][n] fp16 (V, single)
__device__ __half d_yh [Bq * NNp * CIc];              // [b][n][ci] fp16 hi
__device__ __half d_yl [Bq * NNp * CIc];              // [b][n][ci] fp16 lo
__device__ __half d_gwh[CIc * Cc], d_gwl[CIc * Cc];
__device__ __half d_Wwh[Cc * CIc], d_Wwl[Cc * CIc];
__device__ float d_psum[128 * Cc];
__device__ float d_psq [128 * Cc];
__device__ float d_sum[Cc];
__device__ float d_sqs[Cc];

// ---------------- helpers ------------------------------------------------------
__device__ __forceinline__ uint32_t smem_u32(const void* p) {
    uint32_t a;
    asm("{ .reg .u64 t; cvta.to.shared.u64 t, %1; cvt.u32.u64 %0, t; }"
        : "=r"(a) : "l"(p));
    return a;
}
__device__ __forceinline__ void ldsm4(uint32_t* r, uint32_t addr) {
    asm volatile("ldmatrix.sync.aligned.m8n8.x4.shared.b16 {%0,%1,%2,%3}, [%4];"
                 : "=r"(r[0]), "=r"(r[1]), "=r"(r[2]), "=r"(r[3]) : "r"(addr));
}
__device__ __forceinline__ void mma_f16(float* c, const uint32_t* a, const uint32_t* b) {
    asm volatile("mma.sync.aligned.m16n8k16.row.col.f32.f16.f16.f32 "
                 "{%0,%1,%2,%3}, {%4,%5,%6,%7}, {%8,%9}, {%0,%1,%2,%3};"
                 : "+f"(c[0]), "+f"(c[1]), "+f"(c[2]), "+f"(c[3])
                 : "r"(a[0]), "r"(a[1]), "r"(a[2]), "r"(a[3]), "r"(b[0]), "r"(b[1]));
}
__device__ __forceinline__ void cp16(uint32_t s, const void* g) {
    asm volatile("cp.async.cg.shared.global [%0], [%1], 16;" :: "r"(s), "l"(g) : "memory");
}
__device__ __forceinline__ void cp_commit() {
    asm volatile("cp.async.commit_group;" ::: "memory");
}
__device__ __forceinline__ void cp_wait0() {
    asm volatile("cp.async.wait_group 0;" ::: "memory");
}
// pack fp16 pair + residual pair
__device__ __forceinline__ void split2h(float x, float y, uint32_t& h, uint32_t& l) {
    __half xh = __float2half_rn(x);
    __half yh = __float2half_rn(y);
    __half2 hp = __halves2half2(xh, yh);
    h = *reinterpret_cast<uint32_t*>(&hp);
    __half2 lp = __floats2half2_rn(x - __half2float(xh), y - __half2float(yh));
    l = *reinterpret_cast<uint32_t*>(&lp);
}

// [128 rows][64 col] fp16 chunk loader, XOR-swizzled, gmem row stride gs
__device__ __forceinline__ void cp_chunkS(uint32_t sdst, const __half* g, int gs) {
    int t = threadIdx.x;
#pragma unroll
    for (int i = 0; i < 4; i++) {
        int e = t + (i << 8);
        int r = e >> 3, u = e & 7;
        uint32_t su = (uint32_t)(u ^ (r & 7));
        cp16(sdst + ((uint32_t)r << 7) + (su << 4), g + (size_t)r * gs + u * 8);
    }
}

// ---------------- transpose x[b][c][n] -> xfh/xfl[b][n][c] --------------------
__global__ void k_transpose(const float* __restrict__ x) {
    __shared__ float tile[32][33];
    int b  = blockIdx.z;
    int n0 = blockIdx.x * 32;
    int c0 = blockIdx.y * 32;
    int tx = threadIdx.x, ty = threadIdx.y;            // 32 x 8
    const float* xb = x + (size_t)b * Cc * NNp;
#pragma unroll
    for (int j = 0; j < 4; j++) {
        int c = c0 + ty + 8 * j;
        tile[ty + 8 * j][tx] = xb[(size_t)c * NNp + n0 + tx];
    }
    __syncthreads();
    __half* xhb = d_xfh + (size_t)b * NNp * Cc;
    __half* xlb = d_xfl + (size_t)b * NNp * Cc;
#pragma unroll
    for (int j = 0; j < 4; j++) {
        int n = n0 + ty + 8 * j;
        float v = tile[tx][ty + 8 * j];
        size_t o = (size_t)n * Cc + c0 + tx;
        __half h = __float2half_rn(v);
        xhb[o] = h;
        xlb[o] = __float2half_rn(v - __half2float(h));
    }
}

// ---------------- weight splits ------------------------------------------------
__global__ void k_split_w(const float* __restrict__ gw, const float* __restrict__ Ww) {
    int i = blockIdx.x * 256 + threadIdx.x;        // 128 blocks x 256 = 32768
    float v = gw[i];
    __half h = __float2half_rn(v);
    d_gwh[i] = h; d_gwl[i] = __float2half_rn(v - __half2float(h));
    v = Ww[i];
    h = __float2half_rn(v);
    d_Wwh[i] = h; d_Wwl[i] = __float2half_rn(v - __half2float(h));
}

// ---------------- gxT[b][ci][n] = g_w x + g_b  (split-fp16 mma, fp16 out) -----
// A = g_w [128 ci][256 c] resident; B = xfh/xfl [n][c] chunks; C rows=ci, cols=n.
#define GXA_H 0u
#define GXA_L 65536u
#define GXB0  131072u
#define GSMEM 196608

__global__ __launch_bounds__(256, 1) void k_gx_mma(const float* __restrict__ gb) {
    extern __shared__ char sm[];
    uint32_t sb = smem_u32(sm);
    int t = threadIdx.x, L = t & 31, wid = t >> 5;
    int bx = blockIdx.x;
    int b  = bx >> 5;
    int n0 = (bx & 31) << 7;
    const __half* Bh = d_xfh + ((size_t)b * NNp + n0) * Cc;
    const __half* Bl = d_xfl + ((size_t)b * NNp + n0) * Cc;

    // A: 128 rows x 32 units (512B rows)
#pragma unroll
    for (int i = 0; i < 16; i++) {
        int e = t + (i << 8);
        int r = e >> 5, u = e & 31;
        uint32_t su = (uint32_t)(u ^ (r & 7));
        cp16(sb + GXA_H + ((uint32_t)r << 9) + (su << 4), d_gwh + (size_t)r * Cc + u * 8);
        cp16(sb + GXA_L + ((uint32_t)r << 9) + (su << 4), d_gwl + (size_t)r * Cc + u * 8);
    }
    cp_chunkS(sb + GXB0, Bh, Cc);
    cp_chunkS(sb + GXB0 + 16384u, Bl, Cc);
    cp_commit();

    uint32_t qrow = (uint32_t)(16 * wid + (L & 15));
    uint32_t qsw  = qrow & 7;
    uint32_t qk8  = (uint32_t)(L >> 4);
    uint32_t krow = (uint32_t)((L & 7) + ((L >> 4) << 3));
    uint32_t ksw  = krow & 7;
    uint32_t bk   = (uint32_t)((L >> 3) & 1);

    float acc[16][4];
#pragma unroll
    for (int j = 0; j < 16; j++)
#pragma unroll
        for (int q = 0; q < 4; q++) acc[j][q] = 0.f;

    for (int kc = 0; kc < 4; kc++) {
        cp_wait0();
        __syncthreads();
        if (kc < 3) {
            uint32_t nb = GXB0 + ((uint32_t)((kc + 1) & 1)) * 32768u;
            cp_chunkS(sb + nb, Bh + (kc + 1) * 64, Cc);
            cp_chunkS(sb + nb + 16384u, Bl + (kc + 1) * 64, Cc);
            cp_commit();
        }
        uint32_t bbh = sb + GXB0 + ((uint32_t)(kc & 1)) * 32768u;
        uint32_t bbl = bbh + 16384u;
#pragma unroll
        for (int ks = 0; ks < 4; ks++) {
            uint32_t ah[4], al[4], br[8][4];
            uint32_t ku = (uint32_t)(kc * 8 + ks * 2) + qk8;
            uint32_t qa = sb + GXA_H + (qrow << 9) + ((ku ^ qsw) << 4);
            ldsm4(ah, qa);
            ldsm4(al, qa + 65536u);
            uint32_t bsw = (((uint32_t)(ks * 2) + bk) ^ ksw) << 4;
#pragma unroll
            for (int jj = 0; jj < 8; jj++)
                ldsm4(br[jj], bbh + (((uint32_t)(16 * jj) + krow) << 7) + bsw);
#pragma unroll
            for (int j = 0; j < 16; j++) mma_f16(acc[j], ah, &br[j >> 1][(j & 1) * 2]);
#pragma unroll
            for (int j = 0; j < 16; j++) mma_f16(acc[j], al, &br[j >> 1][(j & 1) * 2]);
#pragma unroll
            for (int jj = 0; jj < 8; jj++)
                ldsm4(br[jj], bbl + (((uint32_t)(16 * jj) + krow) << 7) + bsw);
#pragma unroll
            for (int j = 0; j < 16; j++) mma_f16(acc[j], ah, &br[j >> 1][(j & 1) * 2]);
        }
    }

    int ci0 = 16 * wid + (L >> 2);
    float b0 = gb[ci0], b1 = gb[ci0 + 8];
    __half* o = d_gxf + ((size_t)b * CIc + ci0) * NNp + n0;
#pragma unroll
    for (int j = 0; j < 16; j++) {
        int col = 8 * j + 2 * (L & 3);
        __half2 p = __floats2half2_rn(acc[j][0] + b0, acc[j][1] + b0);
        *reinterpret_cast<__half2*>(o + col) = p;
        p = __floats2half2_rn(acc[j][2] + b1, acc[j][3] + b1);
        *reinterpret_cast<__half2*>(o + 8 * NNp + col) = p;
    }
}

// ---------------- wy[b][c][n] = W_w y + W_b  (split-fp16 mma) + BN partials ---
__global__ __launch_bounds__(256, 1) void k_wy_mma(const float* __restrict__ Wb) {
    extern __shared__ char sm[];
    uint32_t sb = smem_u32(sm);
    int t = threadIdx.x, L = t & 31, wid = t >> 5;
    int bx = blockIdx.x;
    int b  = bx >> 5;
    int n0 = (bx & 31) << 7;
    const __half* Bh = d_yh + ((size_t)b * NNp + n0) * CIc;
    const __half* Bl = d_yl + ((size_t)b * NNp + n0) * CIc;

    // A: 256 rows x 16 units (256B rows)
#pragma unroll
    for (int i = 0; i < 16; i++) {
        int e = t + (i << 8);
        int r = e >> 4, u = e & 15;
        uint32_t su = (uint32_t)(u ^ (r & 7));
        cp16(sb + GXA_H + ((uint32_t)r << 8) + (su << 4), d_Wwh + (size_t)r * CIc + u * 8);
        cp16(sb + GXA_L + ((uint32_t)r << 8) + (su << 4), d_Wwl + (size_t)r * CIc + u * 8);
    }
    cp_chunkS(sb + GXB0, Bh, CIc);
    cp_chunkS(sb + GXB0 + 16384u, Bl, CIc);
    cp_commit();

    uint32_t arow0 = (uint32_t)(32 * wid + (L & 15));
    uint32_t qk8   = (uint32_t)(L >> 4);
    uint32_t krow  = (uint32_t)((L & 7) + ((L >> 4) << 3));
    uint32_t ksw   = krow & 7;
    uint32_t bk    = (uint32_t)((L >> 3) & 1);

    float acc[2][16][4];
#pragma unroll
    for (int mt = 0; mt < 2; mt++)
#pragma unroll
        for (int j = 0; j < 16; j++)
#pragma unroll
            for (int q = 0; q < 4; q++) acc[mt][j][q] = 0.f;

    for (int kc = 0; kc < 2; kc++) {
        cp_wait0();
        __syncthreads();
        if (kc < 1) {
            cp_chunkS(sb + GXB0 + 32768u, Bh + 64, CIc);
            cp_chunkS(sb + GXB0 + 49152u, Bl + 64, CIc);
            cp_commit();
        }
        uint32_t bbh = sb + GXB0 + ((uint32_t)kc) * 32768u;
        uint32_t bbl = bbh + 16384u;
#pragma unroll
        for (int ks = 0; ks < 4; ks++) {
            uint32_t ah[2][4], al[2][4], br[8][4];
            uint32_t ku = (uint32_t)(kc * 8 + ks * 2) + qk8;
#pragma unroll
            for (int mt = 0; mt < 2; mt++) {
                uint32_t ar = arow0 + 16u * (uint32_t)mt;
                uint32_t qa = sb + GXA_H + (ar << 8) + ((ku ^ (ar & 7)) << 4);
                ldsm4(ah[mt], qa);
                ldsm4(al[mt], qa + 65536u);
            }
            uint32_t bsw = (((uint32_t)(ks * 2) + bk) ^ ksw) << 4;
#pragma unroll
            for (int jj = 0; jj < 8; jj++)
                ldsm4(br[jj], bbh + (((uint32_t)(16 * jj) + krow) << 7) + bsw);
#pragma unroll
            for (int mt = 0; mt < 2; mt++)
#pragma unroll
                for (int j = 0; j < 16; j++)
                    mma_f16(acc[mt][j], ah[mt], &br[j >> 1][(j & 1) * 2]);
#pragma unroll
            for (int mt = 0; mt < 2; mt++)
#pragma unroll
                for (int j = 0; j < 16; j++)
                    mma_f16(acc[mt][j], al[mt], &br[j >> 1][(j & 1) * 2]);
#pragma unroll
            for (int jj = 0; jj < 8; jj++)
                ldsm4(br[jj], bbl + (((uint32_t)(16 * jj) + krow) << 7) + bsw);
#pragma unroll
            for (int mt = 0; mt < 2; mt++)
#pragma unroll
                for (int j = 0; j < 16; j++)
                    mma_f16(acc[mt][j], ah[mt], &br[j >> 1][(j & 1) * 2]);
        }
    }

    int c0 = 32 * wid + (L >> 2);
    float ps[4], pq[4];
#pragma unroll
    for (int i = 0; i < 4; i++) { ps[i] = 0.f; pq[i] = 0.f; }

#pragma unroll
    for (int mt = 0; mt < 2; mt++) {
        int ca = c0 + 16 * mt, cb = ca + 8;
        float ba = Wb[ca], bb2 = Wb[cb];
        float* oa = d_wy + ((size_t)b * Cc + ca) * NNp + n0;
        float* ob = d_wy + ((size_t)b * Cc + cb) * NNp + n0;
#pragma unroll
        for (int j = 0; j < 16; j++) {
            int col = 8 * j + 2 * (L & 3);
            float v0 = acc[mt][j][0] + ba;
            float v1 = acc[mt][j][1] + ba;
            float v2 = acc[mt][j][2] + bb2;
            float v3 = acc[mt][j][3] + bb2;
            float2 w;
            w.x = v0; w.y = v1;
            *reinterpret_cast<float2*>(oa + col) = w;
            w.x = v2; w.y = v3;
            *reinterpret_cast<float2*>(ob + col) = w;
            ps[mt * 2]     += v0 + v1;
            pq[mt * 2]     += v0 * v0 + v1 * v1;
            ps[mt * 2 + 1] += v2 + v3;
            pq[mt * 2 + 1] += v2 * v2 + v3 * v3;
        }
    }
#pragma unroll
    for (int i = 0; i < 4; i++) {
        ps[i] += __shfl_xor_sync(0xffffffffu, ps[i], 1);
        ps[i] += __shfl_xor_sync(0xffffffffu, ps[i], 2);
        pq[i] += __shfl_xor_sync(0xffffffffu, pq[i], 1);
        pq[i] += __shfl_xor_sync(0xffffffffu, pq[i], 2);
    }
    if ((L & 3) == 0) {
#pragma unroll
        for (int mt = 0; mt < 2; mt++)
#pragma unroll
            for (int qh = 0; qh < 2; qh++) {
                int c = c0 + 16 * mt + 8 * qh;
                d_psum[bx * Cc + c] = ps[mt * 2 + qh];
                d_psq [bx * Cc + c] = pq[mt * 2 + qh];
            }
    }
}

// ---------------- flash attention: fp16, Q split / K single / V single --------
// SMEM: Qh 64KB @0, Ql 64KB @65536, K chunks 16KB: KB0@131072 KB1@147456
//   KB2@163840; V 32KB overlays KB0+KB1 @131072.  FSMEM = 180224.
#define SQH   0u
#define SQL   65536u
#define KB0   131072u
#define KB1   147456u
#define KB2   163840u
#define SV    131072u
#define FSMEM 180224

__device__ __forceinline__ void cp_chunk(uint32_t sdst, const __half* g) {
    cp_chunkS(sdst, g, Cc);
}
__device__ __forceinline__ void cp_v(uint32_t sdst, const __half* g) {
    int t = threadIdx.x;
#pragma unroll
    for (int i = 0; i < 8; i++) {
        int e = t + (i << 8);
        int r = e >> 4, u = e & 15;
        uint32_t su = (uint32_t)(u ^ (r & 7));
        cp16(sdst + ((uint32_t)r << 8) + (su << 4), g + (size_t)r * NNp + u * 8);
    }
}

__global__ __launch_bounds__(256, 1) void k_flash_mma() {
    extern __shared__ char sm[];
    uint32_t sb = smem_u32(sm);
    int t = threadIdx.x;
    int L = t & 31;
    int wid = t >> 5;                  // warp owns rows 16*wid .. +15
    int b  = blockIdx.y;
    int m0 = blockIdx.x * 128;

    const __half* xh = d_xfh + (size_t)b * NNp * Cc;
    const __half* xl = d_xfl + (size_t)b * NNp * Cc;
    const __half* vf = d_gxf + (size_t)b * CIc * NNp;

    // prologue: Q hi+lo + K chunk0 -> KB2
#pragma unroll
    for (int i = 0; i < 16; i++) {
        int e = t + (i << 8);
        int r = e >> 5, u = e & 31;
        uint32_t su = (uint32_t)(u ^ (r & 7));
        cp16(sb + SQH + ((uint32_t)r << 9) + (su << 4), xh + (size_t)(m0 + r) * Cc + u * 8);
        cp16(sb + SQL + ((uint32_t)r << 9) + (su << 4), xl + (size_t)(m0 + r) * Cc + u * 8);
    }
    cp_chunk(sb + KB2, xh);
    cp_commit();

    uint32_t qrow = (uint32_t)(16 * wid + (L & 15));
    uint32_t qsw  = qrow & 7;
    uint32_t qk8  = (uint32_t)(L >> 4);
    uint32_t krow = (uint32_t)((L & 7) + ((L >> 4) << 3));
    uint32_t ksw  = krow & 7;
    uint32_t bk   = (uint32_t)((L >> 3) & 1);

    float Y[16][4];
    float rs0 = 0.f, rs1 = 0.f;
#pragma unroll
    for (int j = 0; j < 16; j++)
#pragma unroll
        for (int q = 0; q < 4; q++) Y[j][q] = 0.f;

    const uint32_t rdB[4] = {KB2, KB0, KB1, KB2};

    for (int kt = 0; kt < NNp; kt += 128) {
        float S[16][4];
#pragma unroll
        for (int j = 0; j < 16; j++)
#pragma unroll
            for (int q = 0; q < 4; q++) S[j][q] = 0.f;

#pragma unroll
        for (int cc = 0; cc < 4; cc++) {
            cp_wait0();
            __syncthreads();
            if (cc == 0) {
                cp_chunk(sb + KB0, xh + (size_t)kt * Cc + 64);
            } else if (cc == 1) {
                cp_chunk(sb + KB1, xh + (size_t)kt * Cc + 128);
            } else if (cc == 2) {
                cp_chunk(sb + KB2, xh + (size_t)kt * Cc + 192);
            } else {
                cp_v(sb + SV, vf + kt);
            }
            cp_commit();
            uint32_t kb = sb + rdB[cc];
#pragma unroll
            for (int ks = 0; ks < 4; ks++) {
                uint32_t ah[4], al[4], br[8][4];
                uint32_t qunit = (uint32_t)(cc * 8 + ks * 2) + qk8;
                uint32_t qa = sb + SQH + (qrow << 9) + (((qunit ^ qsw)) << 4);
                ldsm4(ah, qa);
                ldsm4(al, qa + SQL);
                uint32_t bsw = ((((uint32_t)(ks * 2) + bk) ^ ksw) << 4);
#pragma unroll
                for (int jj = 0; jj < 8; jj++)
                    ldsm4(br[jj], kb + (((uint32_t)(16 * jj) + krow) << 7) + bsw);
#pragma unroll
                for (int j = 0; j < 16; j++) mma_f16(S[j], ah, &br[j >> 1][(j & 1) * 2]);
#pragma unroll
                for (int j = 0; j < 16; j++) mma_f16(S[j], al, &br[j >> 1][(j & 1) * 2]);
            }
        }

        // wait V (issued a full chunk ago), prefetch next tile chunk0 -> KB2
        cp_wait0();
        __syncthreads();
        int kt2 = (kt + 128) & (NNp - 1);
        cp_chunk(sb + KB2, xh + (size_t)kt2 * Cc);
        cp_commit();

        // PV: exp + fp16 split of P, V single digit
#pragma unroll
        for (int ks = 0; ks < 8; ks++) {
            float e00 = __expf(S[2 * ks][0]);
            float e01 = __expf(S[2 * ks][1]);
            float e02 = __expf(S[2 * ks][2]);
            float e03 = __expf(S[2 * ks][3]);
            float e10 = __expf(S[2 * ks + 1][0]);
            float e11 = __expf(S[2 * ks + 1][1]);
            float e12 = __expf(S[2 * ks + 1][2]);
            float e13 = __expf(S[2 * ks + 1][3]);
            rs0 += e00 + e01 + e10 + e11;
            rs1 += e02 + e03 + e12 + e13;
            uint32_t PH[4], PL[4];
            split2h(e00, e01, PH[0], PL[0]);
            split2h(e02, e03, PH[1], PL[1]);
            split2h(e10, e11, PH[2], PL[2]);
            split2h(e12, e13, PH[3], PL[3]);

            uint32_t bv[8][4];
            uint32_t vsw = ((((uint32_t)(ks * 2) + bk) ^ ksw) << 4);
#pragma unroll
            for (int jj = 0; jj < 8; jj++)
                ldsm4(bv[jj], sb + SV + (((uint32_t)(16 * jj) + krow) << 8) + vsw);
#pragma unroll
            for (int j = 0; j < 16; j++) mma_f16(Y[j], PH, &bv[j >> 1][(j & 1) * 2]);
#pragma unroll
            for (int j = 0; j < 16; j++) mma_f16(Y[j], PL, &bv[j >> 1][(j & 1) * 2]);
        }
    }

    // epilogue: rowsums within warp; split-fp16 store of y
    rs0 += __shfl_xor_sync(0xffffffffu, rs0, 1);
    rs0 += __shfl_xor_sync(0xffffffffu, rs0, 2);
    rs1 += __shfl_xor_sync(0xffffffffu, rs1, 1);
    rs1 += __shfl_xor_sync(0xffffffffu, rs1, 2);
    float inv0 = 1.f / rs0;
    float inv1 = 1.f / rs1;

    int r0 = 16 * wid + (L >> 2);
    __half* yh0 = d_yh + ((size_t)b * NNp + m0 + r0) * CIc;
    __half* yl0 = d_yl + ((size_t)b * NNp + m0 + r0) * CIc;
#pragma unroll
    for (int j = 0; j < 16; j++) {
        int col = 8 * j + 2 * (L & 3);
        uint32_t h, l;
        split2h(Y[j][0] * inv0, Y[j][1] * inv0, h, l);
        *reinterpret_cast<uint32_t*>(yh0 + col) = h;
        *reinterpret_cast<uint32_t*>(yl0 + col) = l;
        split2h(Y[j][2] * inv1, Y[j][3] * inv1, h, l);
        *reinterpret_cast<uint32_t*>(yh0 + 8 * CIc + col) = h;
        *reinterpret_cast<uint32_t*>(yl0 + 8 * CIc + col) = l;
    }
}

// ---------------- BN reduce over 128 per-block partials -------------------------
__global__ void k_bnreduce() {
    int c = threadIdx.x;               // 256 threads, 1 block
    float s = 0.f, q = 0.f;
#pragma unroll 8
    for (int bkx = 0; bkx < 128; bkx++) {
        s += d_psum[bkx * Cc + c];
        q += d_psq [bkx * Cc + c];
    }
    d_sum[c] = s;
    d_sqs[c] = q;
}

// ---------------- BN apply + residual (elementwise; wy already [c][n]) --------
__global__ void k_bnfinal2(const float* __restrict__ x,
                           const float* __restrict__ gamma,
                           const float* __restrict__ beta,
                           float* __restrict__ out) {
    size_t base = ((size_t)blockIdx.x * 256 + threadIdx.x) * 4;
    int c = (int)((base >> 12) & 255);
    const float invn = 1.f / (float)(Bq * NNp);
    float mean = d_sum[c] * invn;
    float var  = d_sqs[c] * invn - mean * mean;
    float rsv  = rsqrtf(var + EPSc);
    float g    = gamma[c] * rsv;
    float be   = beta[c] - mean * g;
    float4 w  = *reinterpret_cast<const float4*>(d_wy + base);
    float4 xv = *reinterpret_cast<const float4*>(x + base);
    float4 o;
    o.x = w.x * g + be + xv.x;
    o.y = w.y * g + be + xv.y;
    o.z = w.z * g + be + xv.z;
    o.w = w.w * g + be + xv.w;
    *reinterpret_cast<float4*>(out + base) = o;
}

// ---------------- launch -------------------------------------------------------
extern "C" void kernel_launch(void* const* d_in, const int* in_sizes, int n_in,
                              void* d_out, int out_size) {
    const float* x     = (const float*)d_in[0];
    const float* g_w   = (const float*)d_in[1];
    const float* g_b   = (const float*)d_in[2];
    const float* W_w   = (const float*)d_in[3];
    const float* W_b   = (const float*)d_in[4];
    const float* gamma = (const float*)d_in[5];
    const float* beta  = (const float*)d_in[6];
    float* out = (float*)d_out;

    (void)in_sizes; (void)n_in; (void)out_size;

    cudaFuncSetAttribute(k_flash_mma, cudaFuncAttributeMaxDynamicSharedMemorySize, FSMEM);
    cudaFuncSetAttribute(k_gx_mma, cudaFuncAttributeMaxDynamicSharedMemorySize, GSMEM);
    cudaFuncSetAttribute(k_wy_mma, cudaFuncAttributeMaxDynamicSharedMemorySize, GSMEM);

    k_transpose<<<dim3(NNp / 32, Cc / 32, Bq), dim3(32, 8)>>>(x);
    k_split_w<<<128, 256>>>(g_w, W_w);
    k_gx_mma<<<128, 256, GSMEM>>>(g_b);
    k_flash_mma<<<dim3(NNp / 128, Bq), 256, FSMEM>>>();
    k_wy_mma<<<128, 256, GSMEM>>>(W_b);
    k_bnreduce<<<1, 256>>>();
    k_bnfinal2<<<4096, 256>>>(x, gamma, beta, out);
}

// round 14
// speedup vs baseline: 5.4570x; 1.5091x over previous
#include <cuda_runtime.h>
#include <cuda_fp16.h>
#include <math.h>
#include <stdint.h>
#include <string.h>

#define Bq 4
#define Cc 256
#define CIc 128
#define NNp 4096
#define EPSc 1e-5f

// ---------------- scratch (device globals; no allocations allowed) ------------
__device__ float d_wy[Bq * NNp * Cc];                 // [b][c][n] fp32
__device__ __half d_xfh[Bq * NNp * Cc];               // [b][n][c] fp16 hi
__device__ __half d_xfl[Bq * NNp * Cc];               // [b][n][c] fp16 lo (periphery only)
__device__ __half d_gxf[Bq * CIc * NNp];              // [b][ci][n] fp16 (V, single)
__device__ __half d_yh [Bq * NNp * CIc];              // [b][n][ci] fp16 hi
__device__ __half d_yl [Bq * NNp * CIc];              // [b][n][ci] fp16 lo
__device__ __half d_gwh[CIc * Cc], d_gwl[CIc * Cc];
__device__ __half d_Wwh[Cc * CIc], d_Wwl[Cc * CIc];
__device__ float d_psum[128 * Cc];
__device__ float d_psq [128 * Cc];
__device__ float d_sum[Cc];
__device__ float d_sqs[Cc];

// ---------------- helpers ------------------------------------------------------
__device__ __forceinline__ uint32_t smem_u32(const void* p) {
    uint32_t a;
    asm("{ .reg .u64 t; cvta.to.shared.u64 t, %1; cvt.u32.u64 %0, t; }"
        : "=r"(a) : "l"(p));
    return a;
}
__device__ __forceinline__ void ldsm4(uint32_t* r, uint32_t addr) {
    asm volatile("ldmatrix.sync.aligned.m8n8.x4.shared.b16 {%0,%1,%2,%3}, [%4];"
                 : "=r"(r[0]), "=r"(r[1]), "=r"(r[2]), "=r"(r[3]) : "r"(addr));
}
__device__ __forceinline__ void mma_f16(float* c, const uint32_t* a, const uint32_t* b) {
    asm volatile("mma.sync.aligned.m16n8k16.row.col.f32.f16.f16.f32 "
                 "{%0,%1,%2,%3}, {%4,%5,%6,%7}, {%8,%9}, {%0,%1,%2,%3};"
                 : "+f"(c[0]), "+f"(c[1]), "+f"(c[2]), "+f"(c[3])
                 : "r"(a[0]), "r"(a[1]), "r"(a[2]), "r"(a[3]), "r"(b[0]), "r"(b[1]));
}
__device__ __forceinline__ void cp16(uint32_t s, const void* g) {
    asm volatile("cp.async.cg.shared.global [%0], [%1], 16;" :: "r"(s), "l"(g) : "memory");
}
__device__ __forceinline__ void cp_commit() {
    asm volatile("cp.async.commit_group;" ::: "memory");
}
__device__ __forceinline__ void cp_wait0() {
    asm volatile("cp.async.wait_group 0;" ::: "memory");
}
// pack fp16 pair + residual pair
__device__ __forceinline__ void split2h(float x, float y, uint32_t& h, uint32_t& l) {
    __half xh = __float2half_rn(x);
    __half yh = __float2half_rn(y);
    __half2 hp = __halves2half2(xh, yh);
    h = *reinterpret_cast<uint32_t*>(&hp);
    __half2 lp = __floats2half2_rn(x - __half2float(xh), y - __half2float(yh));
    l = *reinterpret_cast<uint32_t*>(&lp);
}

// [128 rows][64 col] fp16 chunk loader, XOR-swizzled, gmem row stride gs
__device__ __forceinline__ void cp_chunkS(uint32_t sdst, const __half* g, int gs) {
    int t = threadIdx.x;
#pragma unroll
    for (int i = 0; i < 4; i++) {
        int e = t + (i << 8);
        int r = e >> 3, u = e & 7;
        uint32_t su = (uint32_t)(u ^ (r & 7));
        cp16(sdst + ((uint32_t)r << 7) + (su << 4), g + (size_t)r * gs + u * 8);
    }
}

// ---------------- transpose x[b][c][n] -> xfh/xfl[b][n][c] --------------------
__global__ void k_transpose(const float* __restrict__ x) {
    __shared__ float tile[32][33];
    int b  = blockIdx.z;
    int n0 = blockIdx.x * 32;
    int c0 = blockIdx.y * 32;
    int tx = threadIdx.x, ty = threadIdx.y;            // 32 x 8
    const float* xb = x + (size_t)b * Cc * NNp;
#pragma unroll
    for (int j = 0; j < 4; j++) {
        int c = c0 + ty + 8 * j;
        tile[ty + 8 * j][tx] = xb[(size_t)c * NNp + n0 + tx];
    }
    __syncthreads();
    __half* xhb = d_xfh + (size_t)b * NNp * Cc;
    __half* xlb = d_xfl + (size_t)b * NNp * Cc;
#pragma unroll
    for (int j = 0; j < 4; j++) {
        int n = n0 + ty + 8 * j;
        float v = tile[tx][ty + 8 * j];
        size_t o = (size_t)n * Cc + c0 + tx;
        __half h = __float2half_rn(v);
        xhb[o] = h;
        xlb[o] = __float2half_rn(v - __half2float(h));
    }
}

// ---------------- weight splits ------------------------------------------------
__global__ void k_split_w(const float* __restrict__ gw, const float* __restrict__ Ww) {
    int i = blockIdx.x * 256 + threadIdx.x;        // 128 blocks x 256 = 32768
    float v = gw[i];
    __half h = __float2half_rn(v);
    d_gwh[i] = h; d_gwl[i] = __float2half_rn(v - __half2float(h));
    v = Ww[i];
    h = __float2half_rn(v);
    d_Wwh[i] = h; d_Wwl[i] = __float2half_rn(v - __half2float(h));
}

// ---------------- gxT[b][ci][n] = g_w x + g_b  (split-fp16 mma, fp16 out) -----
// A = g_w [128 ci][256 c] resident; B = xfh/xfl [n][c] chunks; C rows=ci, cols=n.
#define GXA_H 0u
#define GXA_L 65536u
#define GXB0  131072u
#define GSMEM 196608

__global__ __launch_bounds__(256, 1) void k_gx_mma(const float* __restrict__ gb) {
    extern __shared__ char sm[];
    uint32_t sb = smem_u32(sm);
    int t = threadIdx.x, L = t & 31, wid = t >> 5;
    int bx = blockIdx.x;
    int b  = bx >> 5;
    int n0 = (bx & 31) << 7;
    const __half* Bh = d_xfh + ((size_t)b * NNp + n0) * Cc;
    const __half* Bl = d_xfl + ((size_t)b * NNp + n0) * Cc;

    // A: 128 rows x 32 units (512B rows)
#pragma unroll
    for (int i = 0; i < 16; i++) {
        int e = t + (i << 8);
        int r = e >> 5, u = e & 31;
        uint32_t su = (uint32_t)(u ^ (r & 7));
        cp16(sb + GXA_H + ((uint32_t)r << 9) + (su << 4), d_gwh + (size_t)r * Cc + u * 8);
        cp16(sb + GXA_L + ((uint32_t)r << 9) + (su << 4), d_gwl + (size_t)r * Cc + u * 8);
    }
    cp_chunkS(sb + GXB0, Bh, Cc);
    cp_chunkS(sb + GXB0 + 16384u, Bl, Cc);
    cp_commit();

    uint32_t qrow = (uint32_t)(16 * wid + (L & 15));
    uint32_t qsw  = qrow & 7;
    uint32_t qk8  = (uint32_t)(L >> 4);
    uint32_t krow = (uint32_t)((L & 7) + ((L >> 4) << 3));
    uint32_t ksw  = krow & 7;
    uint32_t bk   = (uint32_t)((L >> 3) & 1);

    float acc[16][4];
#pragma unroll
    for (int j = 0; j < 16; j++)
#pragma unroll
        for (int q = 0; q < 4; q++) acc[j][q] = 0.f;

    for (int kc = 0; kc < 4; kc++) {
        cp_wait0();
        __syncthreads();
        if (kc < 3) {
            uint32_t nb = GXB0 + ((uint32_t)((kc + 1) & 1)) * 32768u;
            cp_chunkS(sb + nb, Bh + (kc + 1) * 64, Cc);
            cp_chunkS(sb + nb + 16384u, Bl + (kc + 1) * 64, Cc);
            cp_commit();
        }
        uint32_t bbh = sb + GXB0 + ((uint32_t)(kc & 1)) * 32768u;
        uint32_t bbl = bbh + 16384u;
#pragma unroll
        for (int ks = 0; ks < 4; ks++) {
            uint32_t ah[4], al[4], br[8][4];
            uint32_t ku = (uint32_t)(kc * 8 + ks * 2) + qk8;
            uint32_t qa = sb + GXA_H + (qrow << 9) + ((ku ^ qsw) << 4);
            ldsm4(ah, qa);
            ldsm4(al, qa + 65536u);
            uint32_t bsw = (((uint32_t)(ks * 2) + bk) ^ ksw) << 4;
#pragma unroll
            for (int jj = 0; jj < 8; jj++)
                ldsm4(br[jj], bbh + (((uint32_t)(16 * jj) + krow) << 7) + bsw);
#pragma unroll
            for (int j = 0; j < 16; j++) mma_f16(acc[j], ah, &br[j >> 1][(j & 1) * 2]);
#pragma unroll
            for (int j = 0; j < 16; j++) mma_f16(acc[j], al, &br[j >> 1][(j & 1) * 2]);
#pragma unroll
            for (int jj = 0; jj < 8; jj++)
                ldsm4(br[jj], bbl + (((uint32_t)(16 * jj) + krow) << 7) + bsw);
#pragma unroll
            for (int j = 0; j < 16; j++) mma_f16(acc[j], ah, &br[j >> 1][(j & 1) * 2]);
        }
    }

    int ci0 = 16 * wid + (L >> 2);
    float b0 = gb[ci0], b1 = gb[ci0 + 8];
    __half* o = d_gxf + ((size_t)b * CIc + ci0) * NNp + n0;
#pragma unroll
    for (int j = 0; j < 16; j++) {
        int col = 8 * j + 2 * (L & 3);
        __half2 p = __floats2half2_rn(acc[j][0] + b0, acc[j][1] + b0);
        *reinterpret_cast<__half2*>(o + col) = p;
        p = __floats2half2_rn(acc[j][2] + b1, acc[j][3] + b1);
        *reinterpret_cast<__half2*>(o + 8 * NNp + col) = p;
    }
}

// ---------------- wy[b][c][n] = W_w y + W_b  (split-fp16 mma) + BN partials ---
__global__ __launch_bounds__(256, 1) void k_wy_mma(const float* __restrict__ Wb) {
    extern __shared__ char sm[];
    uint32_t sb = smem_u32(sm);
    int t = threadIdx.x, L = t & 31, wid = t >> 5;
    int bx = blockIdx.x;
    int b  = bx >> 5;
    int n0 = (bx & 31) << 7;
    const __half* Bh = d_yh + ((size_t)b * NNp + n0) * CIc;
    const __half* Bl = d_yl + ((size_t)b * NNp + n0) * CIc;

    // A: 256 rows x 16 units (256B rows)
#pragma unroll
    for (int i = 0; i < 16; i++) {
        int e = t + (i << 8);
        int r = e >> 4, u = e & 15;
        uint32_t su = (uint32_t)(u ^ (r & 7));
        cp16(sb + GXA_H + ((uint32_t)r << 8) + (su << 4), d_Wwh + (size_t)r * CIc + u * 8);
        cp16(sb + GXA_L + ((uint32_t)r << 8) + (su << 4), d_Wwl + (size_t)r * CIc + u * 8);
    }
    cp_chunkS(sb + GXB0, Bh, CIc);
    cp_chunkS(sb + GXB0 + 16384u, Bl, CIc);
    cp_commit();

    uint32_t arow0 = (uint32_t)(32 * wid + (L & 15));
    uint32_t qk8   = (uint32_t)(L >> 4);
    uint32_t krow  = (uint32_t)((L & 7) + ((L >> 4) << 3));
    uint32_t ksw   = krow & 7;
    uint32_t bk    = (uint32_t)((L >> 3) & 1);

    float acc[2][16][4];
#pragma unroll
    for (int mt = 0; mt < 2; mt++)
#pragma unroll
        for (int j = 0; j < 16; j++)
#pragma unroll
            for (int q = 0; q < 4; q++) acc[mt][j][q] = 0.f;

    for (int kc = 0; kc < 2; kc++) {
        cp_wait0();
        __syncthreads();
        if (kc < 1) {
            cp_chunkS(sb + GXB0 + 32768u, Bh + 64, CIc);
            cp_chunkS(sb + GXB0 + 49152u, Bl + 64, CIc);
            cp_commit();
        }
        uint32_t bbh = sb + GXB0 + ((uint32_t)kc) * 32768u;
        uint32_t bbl = bbh + 16384u;
#pragma unroll
        for (int ks = 0; ks < 4; ks++) {
            uint32_t ah[2][4], al[2][4], br[8][4];
            uint32_t ku = (uint32_t)(kc * 8 + ks * 2) + qk8;
#pragma unroll
            for (int mt = 0; mt < 2; mt++) {
                uint32_t ar = arow0 + 16u * (uint32_t)mt;
                uint32_t qa = sb + GXA_H + (ar << 8) + ((ku ^ (ar & 7)) << 4);
                ldsm4(ah[mt], qa);
                ldsm4(al[mt], qa + 65536u);
            }
            uint32_t bsw = (((uint32_t)(ks * 2) + bk) ^ ksw) << 4;
#pragma unroll
            for (int jj = 0; jj < 8; jj++)
                ldsm4(br[jj], bbh + (((uint32_t)(16 * jj) + krow) << 7) + bsw);
#pragma unroll
            for (int mt = 0; mt < 2; mt++)
#pragma unroll
                for (int j = 0; j < 16; j++)
                    mma_f16(acc[mt][j], ah[mt], &br[j >> 1][(j & 1) * 2]);
#pragma unroll
            for (int mt = 0; mt < 2; mt++)
#pragma unroll
                for (int j = 0; j < 16; j++)
                    mma_f16(acc[mt][j], al[mt], &br[j >> 1][(j & 1) * 2]);
#pragma unroll
            for (int jj = 0; jj < 8; jj++)
                ldsm4(br[jj], bbl + (((uint32_t)(16 * jj) + krow) << 7) + bsw);
#pragma unroll
            for (int mt = 0; mt < 2; mt++)
#pragma unroll
                for (int j = 0; j < 16; j++)
                    mma_f16(acc[mt][j], ah[mt], &br[j >> 1][(j & 1) * 2]);
        }
    }

    int c0 = 32 * wid + (L >> 2);
    float ps[4], pq[4];
#pragma unroll
    for (int i = 0; i < 4; i++) { ps[i] = 0.f; pq[i] = 0.f; }

#pragma unroll
    for (int mt = 0; mt < 2; mt++) {
        int ca = c0 + 16 * mt, cb = ca + 8;
        float ba = Wb[ca], bb2 = Wb[cb];
        float* oa = d_wy + ((size_t)b * Cc + ca) * NNp + n0;
        float* ob = d_wy + ((size_t)b * Cc + cb) * NNp + n0;
#pragma unroll
        for (int j = 0; j < 16; j++) {
            int col = 8 * j + 2 * (L & 3);
            float v0 = acc[mt][j][0] + ba;
            float v1 = acc[mt][j][1] + ba;
            float v2 = acc[mt][j][2] + bb2;
            float v3 = acc[mt][j][3] + bb2;
            float2 w;
            w.x = v0; w.y = v1;
            *reinterpret_cast<float2*>(oa + col) = w;
            w.x = v2; w.y = v3;
            *reinterpret_cast<float2*>(ob + col) = w;
            ps[mt * 2]     += v0 + v1;
            pq[mt * 2]     += v0 * v0 + v1 * v1;
            ps[mt * 2 + 1] += v2 + v3;
            pq[mt * 2 + 1] += v2 * v2 + v3 * v3;
        }
    }
#pragma unroll
    for (int i = 0; i < 4; i++) {
        ps[i] += __shfl_xor_sync(0xffffffffu, ps[i], 1);
        ps[i] += __shfl_xor_sync(0xffffffffu, ps[i], 2);
        pq[i] += __shfl_xor_sync(0xffffffffu, pq[i], 1);
        pq[i] += __shfl_xor_sync(0xffffffffu, pq[i], 2);
    }
    if ((L & 3) == 0) {
#pragma unroll
        for (int mt = 0; mt < 2; mt++)
#pragma unroll
            for (int qh = 0; qh < 2; qh++) {
                int c = c0 + 16 * mt + 8 * qh;
                d_psum[bx * Cc + c] = ps[mt * 2 + qh];
                d_psq [bx * Cc + c] = pq[mt * 2 + qh];
            }
    }
}

// ---------------- flash attention: pure single-fp16 (Q,K,P,V), fp32 accum -----
// SMEM: Q 64KB @0; K chunks 16KB: KB0@65536 KB1@81920 KB2@98304;
//   V 32KB overlays KB0+KB1 @65536.  FSMEM = 114688.
#define SQH   0u
#define KB0   65536u
#define KB1   81920u
#define KB2   98304u
#define SV    65536u
#define FSMEM 114688

__device__ __forceinline__ void cp_chunk(uint32_t sdst, const __half* g) {
    cp_chunkS(sdst, g, Cc);
}
__device__ __forceinline__ void cp_v(uint32_t sdst, const __half* g) {
    int t = threadIdx.x;
#pragma unroll
    for (int i = 0; i < 8; i++) {
        int e = t + (i << 8);
        int r = e >> 4, u = e & 15;
        uint32_t su = (uint32_t)(u ^ (r & 7));
        cp16(sdst + ((uint32_t)r << 8) + (su << 4), g + (size_t)r * NNp + u * 8);
    }
}

__global__ __launch_bounds__(256, 1) void k_flash_mma() {
    extern __shared__ char sm[];
    uint32_t sb = smem_u32(sm);
    int t = threadIdx.x;
    int L = t & 31;
    int wid = t >> 5;                  // warp owns rows 16*wid .. +15
    int b  = blockIdx.y;
    int m0 = blockIdx.x * 128;

    const __half* xh = d_xfh + (size_t)b * NNp * Cc;
    const __half* vf = d_gxf + (size_t)b * CIc * NNp;

    // prologue: Q (single digit) + K chunk0 -> KB2
#pragma unroll
    for (int i = 0; i < 16; i++) {
        int e = t + (i << 8);
        int r = e >> 5, u = e & 31;
        uint32_t su = (uint32_t)(u ^ (r & 7));
        cp16(sb + SQH + ((uint32_t)r << 9) + (su << 4), xh + (size_t)(m0 + r) * Cc + u * 8);
    }
    cp_chunk(sb + KB2, xh);
    cp_commit();

    uint32_t qrow = (uint32_t)(16 * wid + (L & 15));
    uint32_t qsw  = qrow & 7;
    uint32_t qk8  = (uint32_t)(L >> 4);
    uint32_t krow = (uint32_t)((L & 7) + ((L >> 4) << 3));
    uint32_t ksw  = krow & 7;
    uint32_t bk   = (uint32_t)((L >> 3) & 1);

    float Y[16][4];
    float rs0 = 0.f, rs1 = 0.f;
#pragma unroll
    for (int j = 0; j < 16; j++)
#pragma unroll
        for (int q = 0; q < 4; q++) Y[j][q] = 0.f;

    const uint32_t rdB[4] = {KB2, KB0, KB1, KB2};

    for (int kt = 0; kt < NNp; kt += 128) {
        float S[16][4];
#pragma unroll
        for (int j = 0; j < 16; j++)
#pragma unroll
            for (int q = 0; q < 4; q++) S[j][q] = 0.f;

#pragma unroll
        for (int cc = 0; cc < 4; cc++) {
            cp_wait0();
            __syncthreads();
            if (cc == 0) {
                cp_chunk(sb + KB0, xh + (size_t)kt * Cc + 64);
            } else if (cc == 1) {
                cp_chunk(sb + KB1, xh + (size_t)kt * Cc + 128);
            } else if (cc == 2) {
                cp_chunk(sb + KB2, xh + (size_t)kt * Cc + 192);
            } else {
                cp_v(sb + SV, vf + kt);
            }
            cp_commit();
            uint32_t kb = sb + rdB[cc];
#pragma unroll
            for (int ks = 0; ks < 4; ks++) {
                uint32_t ah[4], br[8][4];
                uint32_t qunit = (uint32_t)(cc * 8 + ks * 2) + qk8;
                uint32_t qa = sb + SQH + (qrow << 9) + (((qunit ^ qsw)) << 4);
                ldsm4(ah, qa);
                uint32_t bsw = ((((uint32_t)(ks * 2) + bk) ^ ksw) << 4);
#pragma unroll
                for (int jj = 0; jj < 8; jj++)
                    ldsm4(br[jj], kb + (((uint32_t)(16 * jj) + krow) << 7) + bsw);
#pragma unroll
                for (int j = 0; j < 16; j++) mma_f16(S[j], ah, &br[j >> 1][(j & 1) * 2]);
            }
        }

        // wait V (issued a full chunk ago), prefetch next tile chunk0 -> KB2
        cp_wait0();
        __syncthreads();
        int kt2 = (kt + 128) & (NNp - 1);
        cp_chunk(sb + KB2, xh + (size_t)kt2 * Cc);
        cp_commit();

        // PV: exp, P single fp16, V single digit
#pragma unroll
        for (int ks = 0; ks < 8; ks++) {
            float e00 = __expf(S[2 * ks][0]);
            float e01 = __expf(S[2 * ks][1]);
            float e02 = __expf(S[2 * ks][2]);
            float e03 = __expf(S[2 * ks][3]);
            float e10 = __expf(S[2 * ks + 1][0]);
            float e11 = __expf(S[2 * ks + 1][1]);
            float e12 = __expf(S[2 * ks + 1][2]);
            float e13 = __expf(S[2 * ks + 1][3]);
            rs0 += e00 + e01 + e10 + e11;
            rs1 += e02 + e03 + e12 + e13;
            uint32_t PH[4];
            __half2 hp;
            hp = __floats2half2_rn(e00, e01); PH[0] = *reinterpret_cast<uint32_t*>(&hp);
            hp = __floats2half2_rn(e02, e03); PH[1] = *reinterpret_cast<uint32_t*>(&hp);
            hp = __floats2half2_rn(e10, e11); PH[2] = *reinterpret_cast<uint32_t*>(&hp);
            hp = __floats2half2_rn(e12, e13); PH[3] = *reinterpret_cast<uint32_t*>(&hp);

            uint32_t bv[8][4];
            uint32_t vsw = ((((uint32_t)(ks * 2) + bk) ^ ksw) << 4);
#pragma unroll
            for (int jj = 0; jj < 8; jj++)
                ldsm4(bv[jj], sb + SV + (((uint32_t)(16 * jj) + krow) << 8) + vsw);
#pragma unroll
            for (int j = 0; j < 16; j++) mma_f16(Y[j], PH, &bv[j >> 1][(j & 1) * 2]);
        }
    }

    // epilogue: rowsums within warp; split-fp16 store of y
    rs0 += __shfl_xor_sync(0xffffffffu, rs0, 1);
    rs0 += __shfl_xor_sync(0xffffffffu, rs0, 2);
    rs1 += __shfl_xor_sync(0xffffffffu, rs1, 1);
    rs1 += __shfl_xor_sync(0xffffffffu, rs1, 2);
    float inv0 = 1.f / rs0;
    float inv1 = 1.f / rs1;

    int r0 = 16 * wid + (L >> 2);
    __half* yh0 = d_yh + ((size_t)b * NNp + m0 + r0) * CIc;
    __half* yl0 = d_yl + ((size_t)b * NNp + m0 + r0) * CIc;
#pragma unroll
    for (int j = 0; j < 16; j++) {
        int col = 8 * j + 2 * (L & 3);
        uint32_t h, l;
        split2h(Y[j][0] * inv0, Y[j][1] * inv0, h, l);
        *reinterpret_cast<uint32_t*>(yh0 + col) = h;
        *reinterpret_cast<uint32_t*>(yl0 + col) = l;
        split2h(Y[j][2] * inv1, Y[j][3] * inv1, h, l);
        *reinterpret_cast<uint32_t*>(yh0 + 8 * CIc + col) = h;
        *reinterpret_cast<uint32_t*>(yl0 + 8 * CIc + col) = l;
    }
}

// ---------------- BN reduce over 128 per-block partials -------------------------
__global__ void k_bnreduce() {
    int c = threadIdx.x;               // 256 threads, 1 block
    float s = 0.f, q = 0.f;
#pragma unroll 8
    for (int bkx = 0; bkx < 128; bkx++) {
        s += d_psum[bkx * Cc + c];
        q += d_psq [bkx * Cc + c];
    }
    d_sum[c] = s;
    d_sqs[c] = q;
}

// ---------------- BN apply + residual (elementwise; wy already [c][n]) --------
__global__ void k_bnfinal2(const float* __restrict__ x,
                           const float* __restrict__ gamma,
                           const float* __restrict__ beta,
                           float* __restrict__ out) {
    size_t base = ((size_t)blockIdx.x * 256 + threadIdx.x) * 4;
    int c = (int)((base >> 12) & 255);
    const float invn = 1.f / (float)(Bq * NNp);
    float mean = d_sum[c] * invn;
    float var  = d_sqs[c] * invn - mean * mean;
    float rsv  = rsqrtf(var + EPSc);
    float g    = gamma[c] * rsv;
    float be   = beta[c] - mean * g;
    float4 w  = *reinterpret_cast<const float4*>(d_wy + base);
    float4 xv = *reinterpret_cast<const float4*>(x + base);
    float4 o;
    o.x = w.x * g + be + xv.x;
    o.y = w.y * g + be + xv.y;
    o.z = w.z * g + be + xv.z;
    o.w = w.w * g + be + xv.w;
    *reinterpret_cast<float4*>(out + base) = o;
}

// ---------------- launch -------------------------------------------------------
extern "C" void kernel_launch(void* const* d_in, const int* in_sizes, int n_in,
                              void* d_out, int out_size) {
    const float* x     = (const float*)d_in[0];
    const float* g_w   = (const float*)d_in[1];
    const float* g_b   = (const float*)d_in[2];
    const float* W_w   = (const float*)d_in[3];
    const float* W_b   = (const float*)d_in[4];
    const float* gamma = (const float*)d_in[5];
    const float* beta  = (const float*)d_in[6];
    float* out = (float*)d_out;

    (void)in_sizes; (void)n_in; (void)out_size;

    cudaFuncSetAttribute(k_flash_mma, cudaFuncAttributeMaxDynamicSharedMemorySize, FSMEM);
    cudaFuncSetAttribute(k_gx_mma, cudaFuncAttributeMaxDynamicSharedMemorySize, GSMEM);
    cudaFuncSetAttribute(k_wy_mma, cudaFuncAttributeMaxDynamicSharedMemorySize, GSMEM);

    k_transpose<<<dim3(NNp / 32, Cc / 32, Bq), dim3(32, 8)>>>(x);
    k_split_w<<<128, 256>>>(g_w, W_w);
    k_gx_mma<<<128, 256, GSMEM>>>(g_b);
    k_flash_mma<<<dim3(NNp / 128, Bq), 256, FSMEM>>>();
    k_wy_mma<<<128, 256, GSMEM>>>(W_b);
    k_bnreduce<<<1, 256>>>();
    k_bnfinal2<<<4096, 256>>>(x, gamma, beta, out);
}

// round 15
// speedup vs baseline: 5.6728x; 1.0395x over previous
#include <cuda_runtime.h>
#include <cuda_fp16.h>
#include <math.h>
#include <stdint.h>
#include <string.h>

#define Bq 4
#define Cc 256
#define CIc 128
#define NNp 4096
#define EPSc 1e-5f

// ---------------- scratch (device globals; no allocations allowed) ------------
__device__ float d_wy[Bq * NNp * Cc];                 // [b][c][n] fp32
__device__ __half d_xfh[Bq * NNp * Cc];               // [b][n][c] fp16
__device__ __half d_gxf[Bq * CIc * NNp];              // [b][ci][n] fp16 (V)
__device__ __half d_yf [Bq * NNp * CIc];              // [b][n][ci] fp16
__device__ __half d_gwh[CIc * Cc], d_gwl[CIc * Cc];
__device__ __half d_Wwh[Cc * CIc], d_Wwl[Cc * CIc];
__device__ float d_psum[128 * Cc];
__device__ float d_psq [128 * Cc];
__device__ float d_sum[Cc];
__device__ float d_sqs[Cc];

// ---------------- helpers ------------------------------------------------------
__device__ __forceinline__ uint32_t smem_u32(const void* p) {
    uint32_t a;
    asm("{ .reg .u64 t; cvta.to.shared.u64 t, %1; cvt.u32.u64 %0, t; }"
        : "=r"(a) : "l"(p));
    return a;
}
__device__ __forceinline__ void ldsm4(uint32_t* r, uint32_t addr) {
    asm volatile("ldmatrix.sync.aligned.m8n8.x4.shared.b16 {%0,%1,%2,%3}, [%4];"
                 : "=r"(r[0]), "=r"(r[1]), "=r"(r[2]), "=r"(r[3]) : "r"(addr));
}
__device__ __forceinline__ void mma_f16(float* c, const uint32_t* a, const uint32_t* b) {
    asm volatile("mma.sync.aligned.m16n8k16.row.col.f32.f16.f16.f32 "
                 "{%0,%1,%2,%3}, {%4,%5,%6,%7}, {%8,%9}, {%0,%1,%2,%3};"
                 : "+f"(c[0]), "+f"(c[1]), "+f"(c[2]), "+f"(c[3])
                 : "r"(a[0]), "r"(a[1]), "r"(a[2]), "r"(a[3]), "r"(b[0]), "r"(b[1]));
}
__device__ __forceinline__ void cp16(uint32_t s, const void* g) {
    asm volatile("cp.async.cg.shared.global [%0], [%1], 16;" :: "r"(s), "l"(g) : "memory");
}
__device__ __forceinline__ void cp_commit() {
    asm volatile("cp.async.commit_group;" ::: "memory");
}
__device__ __forceinline__ void cp_wait0() {
    asm volatile("cp.async.wait_group 0;" ::: "memory");
}
__device__ __forceinline__ void cp_wait1() {
    asm volatile("cp.async.wait_group 1;" ::: "memory");
}

// [128 rows][64 col] fp16 chunk loader, XOR-swizzled, gmem row stride gs
__device__ __forceinline__ void cp_chunkS(uint32_t sdst, const __half* g, int gs) {
    int t = threadIdx.x;
#pragma unroll
    for (int i = 0; i < 4; i++) {
        int e = t + (i << 8);
        int r = e >> 3, u = e & 7;
        uint32_t su = (uint32_t)(u ^ (r & 7));
        cp16(sdst + ((uint32_t)r << 7) + (su << 4), g + (size_t)r * gs + u * 8);
    }
}
// [128 rows][128 col] fp16 loader (256B rows), gmem row stride gs
__device__ __forceinline__ void cp_tile128(uint32_t sdst, const __half* g, int gs) {
    int t = threadIdx.x;
#pragma unroll
    for (int i = 0; i < 8; i++) {
        int e = t + (i << 8);
        int r = e >> 4, u = e & 15;
        uint32_t su = (uint32_t)(u ^ (r & 7));
        cp16(sdst + ((uint32_t)r << 8) + (su << 4), g + (size_t)r * gs + u * 8);
    }
}

// ---------------- transpose x[b][c][n] -> xfh[b][n][c] ------------------------
__global__ void k_transpose(const float* __restrict__ x) {
    __shared__ float tile[32][33];
    int b  = blockIdx.z;
    int n0 = blockIdx.x * 32;
    int c0 = blockIdx.y * 32;
    int tx = threadIdx.x, ty = threadIdx.y;            // 32 x 8
    const float* xb = x + (size_t)b * Cc * NNp;
#pragma unroll
    for (int j = 0; j < 4; j++) {
        int c = c0 + ty + 8 * j;
        tile[ty + 8 * j][tx] = xb[(size_t)c * NNp + n0 + tx];
    }
    __syncthreads();
    __half* xhb = d_xfh + (size_t)b * NNp * Cc;
#pragma unroll
    for (int j = 0; j < 4; j++) {
        int n = n0 + ty + 8 * j;
        float v = tile[tx][ty + 8 * j];
        xhb[(size_t)n * Cc + c0 + tx] = __float2half_rn(v);
    }
}

// ---------------- weight splits ------------------------------------------------
__global__ void k_split_w(const float* __restrict__ gw, const float* __restrict__ Ww) {
    int i = blockIdx.x * 256 + threadIdx.x;        // 128 blocks x 256 = 32768
    float v = gw[i];
    __half h = __float2half_rn(v);
    d_gwh[i] = h; d_gwl[i] = __float2half_rn(v - __half2float(h));
    v = Ww[i];
    h = __float2half_rn(v);
    d_Wwh[i] = h; d_Wwl[i] = __float2half_rn(v - __half2float(h));
}

// ---------------- gxT[b][ci][n] = g_w x + g_b  (A split, B single) ------------
// A = g_w [128 ci][256 c] hi/lo resident; B = xfh [n][c] chunks; C rows=ci, cols=n.
#define GXA_H 0u
#define GXA_L 65536u
#define GXB0  131072u
#define GXB1  147456u
#define GSMEM 163840

__global__ __launch_bounds__(256, 1) void k_gx_mma(const float* __restrict__ gb) {
    extern __shared__ char sm[];
    uint32_t sb = smem_u32(sm);
    int t = threadIdx.x, L = t & 31, wid = t >> 5;
    int bx = blockIdx.x;
    int b  = bx >> 5;
    int n0 = (bx & 31) << 7;
    const __half* Bh = d_xfh + ((size_t)b * NNp + n0) * Cc;

    // A: 128 rows x 32 units (512B rows)
#pragma unroll
    for (int i = 0; i < 16; i++) {
        int e = t + (i << 8);
        int r = e >> 5, u = e & 31;
        uint32_t su = (uint32_t)(u ^ (r & 7));
        cp16(sb + GXA_H + ((uint32_t)r << 9) + (su << 4), d_gwh + (size_t)r * Cc + u * 8);
        cp16(sb + GXA_L + ((uint32_t)r << 9) + (su << 4), d_gwl + (size_t)r * Cc + u * 8);
    }
    cp_chunkS(sb + GXB0, Bh, Cc);
    cp_commit();

    uint32_t qrow = (uint32_t)(16 * wid + (L & 15));
    uint32_t qsw  = qrow & 7;
    uint32_t qk8  = (uint32_t)(L >> 4);
    uint32_t krow = (uint32_t)((L & 7) + ((L >> 4) << 3));
    uint32_t ksw  = krow & 7;
    uint32_t bk   = (uint32_t)((L >> 3) & 1);

    float acc[16][4];
#pragma unroll
    for (int j = 0; j < 16; j++)
#pragma unroll
        for (int q = 0; q < 4; q++) acc[j][q] = 0.f;

    for (int kc = 0; kc < 4; kc++) {
        cp_wait0();
        __syncthreads();
        if (kc < 3) {
            cp_chunkS(sb + ((kc & 1) ? GXB0 : GXB1), Bh + (kc + 1) * 64, Cc);
            cp_commit();
        }
        uint32_t bb = sb + ((kc & 1) ? GXB1 : GXB0);
#pragma unroll
        for (int ks = 0; ks < 4; ks++) {
            uint32_t ah[4], al[4], br[8][4];
            uint32_t ku = (uint32_t)(kc * 8 + ks * 2) + qk8;
            uint32_t qa = sb + GXA_H + (qrow << 9) + ((ku ^ qsw) << 4);
            ldsm4(ah, qa);
            ldsm4(al, qa + 65536u);
            uint32_t bsw = (((uint32_t)(ks * 2) + bk) ^ ksw) << 4;
#pragma unroll
            for (int jj = 0; jj < 8; jj++)
                ldsm4(br[jj], bb + (((uint32_t)(16 * jj) + krow) << 7) + bsw);
#pragma unroll
            for (int j = 0; j < 16; j++) mma_f16(acc[j], ah, &br[j >> 1][(j & 1) * 2]);
#pragma unroll
            for (int j = 0; j < 16; j++) mma_f16(acc[j], al, &br[j >> 1][(j & 1) * 2]);
        }
    }

    int ci0 = 16 * wid + (L >> 2);
    float b0 = gb[ci0], b1 = gb[ci0 + 8];
    __half* o = d_gxf + ((size_t)b * CIc + ci0) * NNp + n0;
#pragma unroll
    for (int j = 0; j < 16; j++) {
        int col = 8 * j + 2 * (L & 3);
        __half2 p = __floats2half2_rn(acc[j][0] + b0, acc[j][1] + b0);
        *reinterpret_cast<__half2*>(o + col) = p;
        p = __floats2half2_rn(acc[j][2] + b1, acc[j][3] + b1);
        *reinterpret_cast<__half2*>(o + 8 * NNp + col) = p;
    }
}

// ---------------- wy[b][c][n] = W_w y + W_b  (A split, B single) + BN partials -
__global__ __launch_bounds__(256, 1) void k_wy_mma(const float* __restrict__ Wb) {
    extern __shared__ char sm[];
    uint32_t sb = smem_u32(sm);
    int t = threadIdx.x, L = t & 31, wid = t >> 5;
    int bx = blockIdx.x;
    int b  = bx >> 5;
    int n0 = (bx & 31) << 7;
    const __half* Bh = d_yf + ((size_t)b * NNp + n0) * CIc;

    // A: 256 rows x 16 units (256B rows)
#pragma unroll
    for (int i = 0; i < 16; i++) {
        int e = t + (i << 8);
        int r = e >> 4, u = e & 15;
        uint32_t su = (uint32_t)(u ^ (r & 7));
        cp16(sb + GXA_H + ((uint32_t)r << 8) + (su << 4), d_Wwh + (size_t)r * CIc + u * 8);
        cp16(sb + GXA_L + ((uint32_t)r << 8) + (su << 4), d_Wwl + (size_t)r * CIc + u * 8);
    }
    cp_chunkS(sb + GXB0, Bh, CIc);
    cp_commit();

    uint32_t arow0 = (uint32_t)(32 * wid + (L & 15));
    uint32_t qk8   = (uint32_t)(L >> 4);
    uint32_t krow  = (uint32_t)((L & 7) + ((L >> 4) << 3));
    uint32_t ksw   = krow & 7;
    uint32_t bk    = (uint32_t)((L >> 3) & 1);

    float acc[2][16][4];
#pragma unroll
    for (int mt = 0; mt < 2; mt++)
#pragma unroll
        for (int j = 0; j < 16; j++)
#pragma unroll
            for (int q = 0; q < 4; q++) acc[mt][j][q] = 0.f;

    for (int kc = 0; kc < 2; kc++) {
        cp_wait0();
        __syncthreads();
        if (kc < 1) {
            cp_chunkS(sb + GXB1, Bh + 64, CIc);
            cp_commit();
        }
        uint32_t bb = sb + (kc ? GXB1 : GXB0);
#pragma unroll
        for (int ks = 0; ks < 4; ks++) {
            uint32_t ah[2][4], al[2][4], br[8][4];
            uint32_t ku = (uint32_t)(kc * 8 + ks * 2) + qk8;
#pragma unroll
            for (int mt = 0; mt < 2; mt++) {
                uint32_t ar = arow0 + 16u * (uint32_t)mt;
                uint32_t qa = sb + GXA_H + (ar << 8) + ((ku ^ (ar & 7)) << 4);
                ldsm4(ah[mt], qa);
                ldsm4(al[mt], qa + 65536u);
            }
            uint32_t bsw = (((uint32_t)(ks * 2) + bk) ^ ksw) << 4;
#pragma unroll
            for (int jj = 0; jj < 8; jj++)
                ldsm4(br[jj], bb + (((uint32_t)(16 * jj) + krow) << 7) + bsw);
#pragma unroll
            for (int mt = 0; mt < 2; mt++)
#pragma unroll
                for (int j = 0; j < 16; j++)
                    mma_f16(acc[mt][j], ah[mt], &br[j >> 1][(j & 1) * 2]);
#pragma unroll
            for (int mt = 0; mt < 2; mt++)
#pragma unroll
                for (int j = 0; j < 16; j++)
                    mma_f16(acc[mt][j], al[mt], &br[j >> 1][(j & 1) * 2]);
        }
    }

    int c0 = 32 * wid + (L >> 2);
    float ps[4], pq[4];
#pragma unroll
    for (int i = 0; i < 4; i++) { ps[i] = 0.f; pq[i] = 0.f; }

#pragma unroll
    for (int mt = 0; mt < 2; mt++) {
        int ca = c0 + 16 * mt, cb = ca + 8;
        float ba = Wb[ca], bb2 = Wb[cb];
        float* oa = d_wy + ((size_t)b * Cc + ca) * NNp + n0;
        float* ob = d_wy + ((size_t)b * Cc + cb) * NNp + n0;
#pragma unroll
        for (int j = 0; j < 16; j++) {
            int col = 8 * j + 2 * (L & 3);
            float v0 = acc[mt][j][0] + ba;
            float v1 = acc[mt][j][1] + ba;
            float v2 = acc[mt][j][2] + bb2;
            float v3 = acc[mt][j][3] + bb2;
            float2 w;
            w.x = v0; w.y = v1;
            *reinterpret_cast<float2*>(oa + col) = w;
            w.x = v2; w.y = v3;
            *reinterpret_cast<float2*>(ob + col) = w;
            ps[mt * 2]     += v0 + v1;
            pq[mt * 2]     += v0 * v0 + v1 * v1;
            ps[mt * 2 + 1] += v2 + v3;
            pq[mt * 2 + 1] += v2 * v2 + v3 * v3;
        }
    }
#pragma unroll
    for (int i = 0; i < 4; i++) {
        ps[i] += __shfl_xor_sync(0xffffffffu, ps[i], 1);
        ps[i] += __shfl_xor_sync(0xffffffffu, ps[i], 2);
        pq[i] += __shfl_xor_sync(0xffffffffu, pq[i], 1);
        pq[i] += __shfl_xor_sync(0xffffffffu, pq[i], 2);
    }
    if ((L & 3) == 0) {
#pragma unroll
        for (int mt = 0; mt < 2; mt++)
#pragma unroll
            for (int qh = 0; qh < 2; qh++) {
                int c = c0 + 16 * mt + 8 * qh;
                d_psum[bx * Cc + c] = ps[mt * 2 + qh];
                d_psq [bx * Cc + c] = pq[mt * 2 + qh];
            }
    }
}

// ---------------- flash attention: single fp16; 3-phase wait_group-1 pipeline --
// SMEM: Q 64KB @0; KA 32KB @65536; KB 32KB @98304; V 32KB @131072.
#define SQH   0u
#define SKA   65536u
#define SKB   98304u
#define SV    131072u
#define FSMEM 163840

__global__ __launch_bounds__(256, 1) void k_flash_mma() {
    extern __shared__ char sm[];
    uint32_t sb = smem_u32(sm);
    int t = threadIdx.x;
    int L = t & 31;
    int wid = t >> 5;                  // warp owns rows 16*wid .. +15
    int b  = blockIdx.y;
    int m0 = blockIdx.x * 128;

    const __half* xh = d_xfh + (size_t)b * NNp * Cc;
    const __half* vf = d_gxf + (size_t)b * CIc * NNp;

    // prologue: Q + K(t0, c0:128) -> KA  [group1]; K(t0, c128:256) -> KB [group2]
#pragma unroll
    for (int i = 0; i < 16; i++) {
        int e = t + (i << 8);
        int r = e >> 5, u = e & 31;
        uint32_t su = (uint32_t)(u ^ (r & 7));
        cp16(sb + SQH + ((uint32_t)r << 9) + (su << 4), xh + (size_t)(m0 + r) * Cc + u * 8);
    }
    cp_tile128(sb + SKA, xh, Cc);
    cp_commit();
    cp_tile128(sb + SKB, xh + 128, Cc);
    cp_commit();

    uint32_t qrow = (uint32_t)(16 * wid + (L & 15));
    uint32_t qsw  = qrow & 7;
    uint32_t qk8  = (uint32_t)(L >> 4);
    uint32_t krow = (uint32_t)((L & 7) + ((L >> 4) << 3));
    uint32_t ksw  = krow & 7;
    uint32_t bk   = (uint32_t)((L >> 3) & 1);

    float Y[16][4];
    float rs0 = 0.f, rs1 = 0.f;
#pragma unroll
    for (int j = 0; j < 16; j++)
#pragma unroll
        for (int q = 0; q < 4; q++) Y[j][q] = 0.f;

    for (int kt = 0; kt < NNp; kt += 128) {
        int kt2 = (kt + 128) & (NNp - 1);
        float S[16][4];
#pragma unroll
        for (int j = 0; j < 16; j++)
#pragma unroll
            for (int q = 0; q < 4; q++) S[j][q] = 0.f;

        // ---- phase 1: KA ready; issue V; QK on c 0..127 ----
        cp_wait1();
        __syncthreads();
        cp_v_issue: ;
        cp_tile128(sb + SV, vf + kt, NNp);
        cp_commit();
#pragma unroll
        for (int ks = 0; ks < 8; ks++) {
            uint32_t ah[4], br[8][4];
            uint32_t qunit = (uint32_t)(ks * 2) + qk8;
            ldsm4(ah, sb + SQH + (qrow << 9) + ((qunit ^ qsw) << 4));
            uint32_t bsw = ((((uint32_t)(ks * 2) + bk) ^ ksw) << 4);
#pragma unroll
            for (int jj = 0; jj < 8; jj++)
                ldsm4(br[jj], sb + SKA + (((uint32_t)(16 * jj) + krow) << 8) + bsw);
#pragma unroll
            for (int j = 0; j < 16; j++) mma_f16(S[j], ah, &br[j >> 1][(j & 1) * 2]);
        }

        // ---- phase 2: KB ready; issue next-tile KA; QK on c 128..255 ----
        cp_wait1();
        __syncthreads();
        cp_tile128(sb + SKA, xh + (size_t)kt2 * Cc, Cc);
        cp_commit();
#pragma unroll
        for (int ks = 0; ks < 8; ks++) {
            uint32_t ah[4], br[8][4];
            uint32_t qunit = (uint32_t)(16 + ks * 2) + qk8;
            ldsm4(ah, sb + SQH + (qrow << 9) + ((qunit ^ qsw) << 4));
            uint32_t bsw = ((((uint32_t)(ks * 2) + bk) ^ ksw) << 4);
#pragma unroll
            for (int jj = 0; jj < 8; jj++)
                ldsm4(br[jj], sb + SKB + (((uint32_t)(16 * jj) + krow) << 8) + bsw);
#pragma unroll
            for (int j = 0; j < 16; j++) mma_f16(S[j], ah, &br[j >> 1][(j & 1) * 2]);
        }

        // ---- phase 3: V ready; issue next-tile KB; exp + PV ----
        cp_wait1();
        __syncthreads();
        cp_tile128(sb + SKB, xh + (size_t)kt2 * Cc + 128, Cc);
        cp_commit();
#pragma unroll
        for (int ks = 0; ks < 8; ks++) {
            float e00 = __expf(S[2 * ks][0]);
            float e01 = __expf(S[2 * ks][1]);
            float e02 = __expf(S[2 * ks][2]);
            float e03 = __expf(S[2 * ks][3]);
            float e10 = __expf(S[2 * ks + 1][0]);
            float e11 = __expf(S[2 * ks + 1][1]);
            float e12 = __expf(S[2 * ks + 1][2]);
            float e13 = __expf(S[2 * ks + 1][3]);
            rs0 += e00 + e01 + e10 + e11;
            rs1 += e02 + e03 + e12 + e13;
            uint32_t PH[4];
            __half2 hp;
            hp = __floats2half2_rn(e00, e01); PH[0] = *reinterpret_cast<uint32_t*>(&hp);
            hp = __floats2half2_rn(e02, e03); PH[1] = *reinterpret_cast<uint32_t*>(&hp);
            hp = __floats2half2_rn(e10, e11); PH[2] = *reinterpret_cast<uint32_t*>(&hp);
            hp = __floats2half2_rn(e12, e13); PH[3] = *reinterpret_cast<uint32_t*>(&hp);

            uint32_t bv[8][4];
            uint32_t vsw = ((((uint32_t)(ks * 2) + bk) ^ ksw) << 4);
#pragma unroll
            for (int jj = 0; jj < 8; jj++)
                ldsm4(bv[jj], sb + SV + (((uint32_t)(16 * jj) + krow) << 8) + vsw);
#pragma unroll
            for (int j = 0; j < 16; j++) mma_f16(Y[j], PH, &bv[j >> 1][(j & 1) * 2]);
        }
    }

    // epilogue: rowsums within warp; single-fp16 store of y
    rs0 += __shfl_xor_sync(0xffffffffu, rs0, 1);
    rs0 += __shfl_xor_sync(0xffffffffu, rs0, 2);
    rs1 += __shfl_xor_sync(0xffffffffu, rs1, 1);
    rs1 += __shfl_xor_sync(0xffffffffu, rs1, 2);
    float inv0 = 1.f / rs0;
    float inv1 = 1.f / rs1;

    int r0 = 16 * wid + (L >> 2);
    __half* yf0 = d_yf + ((size_t)b * NNp + m0 + r0) * CIc;
#pragma unroll
    for (int j = 0; j < 16; j++) {
        int col = 8 * j + 2 * (L & 3);
        __half2 p = __floats2half2_rn(Y[j][0] * inv0, Y[j][1] * inv0);
        *reinterpret_cast<__half2*>(yf0 + col) = p;
        p = __floats2half2_rn(Y[j][2] * inv1, Y[j][3] * inv1);
        *reinterpret_cast<__half2*>(yf0 + 8 * CIc + col) = p;
    }
}

// ---------------- BN reduce over 128 per-block partials -------------------------
__global__ void k_bnreduce() {
    int c = threadIdx.x;               // 256 threads, 1 block
    float s = 0.f, q = 0.f;
#pragma unroll 8
    for (int bkx = 0; bkx < 128; bkx++) {
        s += d_psum[bkx * Cc + c];
        q += d_psq [bkx * Cc + c];
    }
    d_sum[c] = s;
    d_sqs[c] = q;
}

// ---------------- BN apply + residual (elementwise; wy already [c][n]) --------
__global__ void k_bnfinal2(const float* __restrict__ x,
                           const float* __restrict__ gamma,
                           const float* __restrict__ beta,
                           float* __restrict__ out) {
    size_t base = ((size_t)blockIdx.x * 256 + threadIdx.x) * 4;
    int c = (int)((base >> 12) & 255);
    const float invn = 1.f / (float)(Bq * NNp);
    float mean = d_sum[c] * invn;
    float var  = d_sqs[c] * invn - mean * mean;
    float rsv  = rsqrtf(var + EPSc);
    float g    = gamma[c] * rsv;
    float be   = beta[c] - mean * g;
    float4 w  = *reinterpret_cast<const float4*>(d_wy + base);
    float4 xv = *reinterpret_cast<const float4*>(x + base);
    float4 o;
    o.x = w.x * g + be + xv.x;
    o.y = w.y * g + be + xv.y;
    o.z = w.z * g + be + xv.z;
    o.w = w.w * g + be + xv.w;
    *reinterpret_cast<float4*>(out + base) = o;
}

// ---------------- launch -------------------------------------------------------
extern "C" void kernel_launch(void* const* d_in, const int* in_sizes, int n_in,
                              void* d_out, int out_size) {
    const float* x     = (const float*)d_in[0];
    const float* g_w   = (const float*)d_in[1];
    const float* g_b   = (const float*)d_in[2];
    const float* W_w   = (const float*)d_in[3];
    const float* W_b   = (const float*)d_in[4];
    const float* gamma = (const float*)d_in[5];
    const float* beta  = (const float*)d_in[6];
    float* out = (float*)d_out;

    (void)in_sizes; (void)n_in; (void)out_size;

    cudaFuncSetAttribute(k_flash_mma, cudaFuncAttributeMaxDynamicSharedMemorySize, FSMEM);
    cudaFuncSetAttribute(k_gx_mma, cudaFuncAttributeMaxDynamicSharedMemorySize, GSMEM);
    cudaFuncSetAttribute(k_wy_mma, cudaFuncAttributeMaxDynamicSharedMemorySize, GSMEM);

    k_transpose<<<dim3(NNp / 32, Cc / 32, Bq), dim3(32, 8)>>>(x);
    k_split_w<<<128, 256>>>(g_w, W_w);
    k_gx_mma<<<128, 256, GSMEM>>>(g_b);
    k_flash_mma<<<dim3(NNp / 128, Bq), 256, FSMEM>>>();
    k_wy_mma<<<128, 256, GSMEM>>>(W_b);
    k_bnreduce<<<1, 256>>>();
    k_bnfinal2<<<4096, 256>>>(x, gamma, beta, out);
}

// round 17
// speedup vs baseline: 5.7767x; 1.0183x over previous
#include <cuda_runtime.h>
#include <cuda_fp16.h>
#include <math.h>
#include <stdint.h>
#include <string.h>

#define Bq 4
#define Cc 256
#define CIc 128
#define NNp 4096
#define EPSc 1e-5f

// ---------------- scratch (device globals; no allocations allowed) ------------
__device__ __half d_wyh[Bq * NNp * Cc];               // [b][c][n] fp16
__device__ __half d_xfh[Bq * NNp * Cc];               // [b][n][c] fp16
__device__ __half d_gxf[Bq * CIc * NNp];              // [b][ci][n] fp16 (V)
__device__ __half d_yf [Bq * NNp * CIc];              // [b][n][ci] fp16
__device__ __half d_gwh[CIc * Cc], d_gwl[CIc * Cc];
__device__ __half d_Wwh[Cc * CIc], d_Wwl[Cc * CIc];
__device__ float d_psum[128 * Cc];
__device__ float d_psq [128 * Cc];
__device__ float d_sum[Cc];
__device__ float d_sqs[Cc];

// ---------------- helpers ------------------------------------------------------
__device__ __forceinline__ uint32_t smem_u32(const void* p) {
    uint32_t a;
    asm("{ .reg .u64 t; cvta.to.shared.u64 t, %1; cvt.u32.u64 %0, t; }"
        : "=r"(a) : "l"(p));
    return a;
}
__device__ __forceinline__ void ldsm4(uint32_t* r, uint32_t addr) {
    asm volatile("ldmatrix.sync.aligned.m8n8.x4.shared.b16 {%0,%1,%2,%3}, [%4];"
                 : "=r"(r[0]), "=r"(r[1]), "=r"(r[2]), "=r"(r[3]) : "r"(addr));
}
__device__ __forceinline__ void mma_f16(float* c, const uint32_t* a, const uint32_t* b) {
    asm volatile("mma.sync.aligned.m16n8k16.row.col.f32.f16.f16.f32 "
                 "{%0,%1,%2,%3}, {%4,%5,%6,%7}, {%8,%9}, {%0,%1,%2,%3};"
                 : "+f"(c[0]), "+f"(c[1]), "+f"(c[2]), "+f"(c[3])
                 : "r"(a[0]), "r"(a[1]), "r"(a[2]), "r"(a[3]), "r"(b[0]), "r"(b[1]));
}
__device__ __forceinline__ void cp16(uint32_t s, const void* g) {
    asm volatile("cp.async.cg.shared.global [%0], [%1], 16;" :: "r"(s), "l"(g) : "memory");
}
__device__ __forceinline__ void cp_commit() {
    asm volatile("cp.async.commit_group;" ::: "memory");
}
__device__ __forceinline__ void cp_wait0() {
    asm volatile("cp.async.wait_group 0;" ::: "memory");
}
__device__ __forceinline__ void cp_wait1() {
    asm volatile("cp.async.wait_group 1;" ::: "memory");
}

// [128 rows][64 col] fp16 chunk loader (128B rows), XOR-swizzled
__device__ __forceinline__ void cp_chunkS(uint32_t sdst, const __half* g, int gs) {
    int t = threadIdx.x;
#pragma unroll
    for (int i = 0; i < 4; i++) {
        int e = t + (i << 8);
        int r = e >> 3, u = e & 7;
        uint32_t su = (uint32_t)(u ^ (r & 7));
        cp16(sdst + ((uint32_t)r << 7) + (su << 4), g + (size_t)r * gs + u * 8);
    }
}
// [128 rows][128 col] fp16 loader (256B rows)
__device__ __forceinline__ void cp_tile128(uint32_t sdst, const __half* g, int gs) {
    int t = threadIdx.x;
#pragma unroll
    for (int i = 0; i < 8; i++) {
        int e = t + (i << 8);
        int r = e >> 4, u = e & 15;
        uint32_t su = (uint32_t)(u ^ (r & 7));
        cp16(sdst + ((uint32_t)r << 8) + (su << 4), g + (size_t)r * gs + u * 8);
    }
}
// [128 rows][256 col] fp16 loader (512B rows)
__device__ __forceinline__ void cp_tile256(uint32_t sdst, const __half* g, int gs) {
    int t = threadIdx.x;
#pragma unroll
    for (int i = 0; i < 16; i++) {
        int e = t + (i << 8);
        int r = e >> 5, u = e & 31;
        uint32_t su = (uint32_t)(u ^ (r & 7));
        cp16(sdst + ((uint32_t)r << 9) + (su << 4), g + (size_t)r * gs + u * 8);
    }
}

// ---------------- transpose x[b][c][n] -> xfh[b][n][c] ------------------------
__global__ void k_transpose(const float* __restrict__ x) {
    __shared__ float tile[32][33];
    int b  = blockIdx.z;
    int n0 = blockIdx.x * 32;
    int c0 = blockIdx.y * 32;
    int tx = threadIdx.x, ty = threadIdx.y;            // 32 x 8
    const float* xb = x + (size_t)b * Cc * NNp;
#pragma unroll
    for (int j = 0; j < 4; j++) {
        int c = c0 + ty + 8 * j;
        tile[ty + 8 * j][tx] = xb[(size_t)c * NNp + n0 + tx];
    }
    __syncthreads();
    __half* xhb = d_xfh + (size_t)b * NNp * Cc;
#pragma unroll
    for (int j = 0; j < 4; j++) {
        int n = n0 + ty + 8 * j;
        float v = tile[tx][ty + 8 * j];
        xhb[(size_t)n * Cc + c0 + tx] = __float2half_rn(v);
    }
}

// ---------------- weight splits ------------------------------------------------
__global__ void k_split_w(const float* __restrict__ gw, const float* __restrict__ Ww) {
    int i = blockIdx.x * 256 + threadIdx.x;        // 128 blocks x 256 = 32768
    float v = gw[i];
    __half h = __float2half_rn(v);
    d_gwh[i] = h; d_gwl[i] = __float2half_rn(v - __half2float(h));
    v = Ww[i];
    h = __float2half_rn(v);
    d_Wwh[i] = h; d_Wwl[i] = __float2half_rn(v - __half2float(h));
}

// ---------------- gxT[b][ci][n] = g_w x + g_b  (A split, B single) ------------
#define GXA_H 0u
#define GXA_L 65536u
#define GXB0  131072u
#define GXB1  147456u
#define GSMEM 163840

__global__ __launch_bounds__(256, 1) void k_gx_mma(const float* __restrict__ gb) {
    extern __shared__ char sm[];
    uint32_t sb = smem_u32(sm);
    int t = threadIdx.x, L = t & 31, wid = t >> 5;
    int bx = blockIdx.x;
    int b  = bx >> 5;
    int n0 = (bx & 31) << 7;
    const __half* Bh = d_xfh + ((size_t)b * NNp + n0) * Cc;

#pragma unroll
    for (int i = 0; i < 16; i++) {
        int e = t + (i << 8);
        int r = e >> 5, u = e & 31;
        uint32_t su = (uint32_t)(u ^ (r & 7));
        cp16(sb + GXA_H + ((uint32_t)r << 9) + (su << 4), d_gwh + (size_t)r * Cc + u * 8);
        cp16(sb + GXA_L + ((uint32_t)r << 9) + (su << 4), d_gwl + (size_t)r * Cc + u * 8);
    }
    cp_chunkS(sb + GXB0, Bh, Cc);
    cp_commit();

    uint32_t qrow = (uint32_t)(16 * wid + (L & 15));
    uint32_t qsw  = qrow & 7;
    uint32_t qk8  = (uint32_t)(L >> 4);
    uint32_t krow = (uint32_t)((L & 7) + ((L >> 4) << 3));
    uint32_t ksw  = krow & 7;
    uint32_t bk   = (uint32_t)((L >> 3) & 1);

    float acc[16][4];
#pragma unroll
    for (int j = 0; j < 16; j++)
#pragma unroll
        for (int q = 0; q < 4; q++) acc[j][q] = 0.f;

    for (int kc = 0; kc < 4; kc++) {
        cp_wait0();
        __syncthreads();
        if (kc < 3) {
            cp_chunkS(sb + ((kc & 1) ? GXB0 : GXB1), Bh + (kc + 1) * 64, Cc);
            cp_commit();
        }
        uint32_t bb = sb + ((kc & 1) ? GXB1 : GXB0);
#pragma unroll
        for (int ks = 0; ks < 4; ks++) {
            uint32_t ah[4], al[4], br[8][4];
            uint32_t ku = (uint32_t)(kc * 8 + ks * 2) + qk8;
            uint32_t qa = sb + GXA_H + (qrow << 9) + ((ku ^ qsw) << 4);
            ldsm4(ah, qa);
            ldsm4(al, qa + 65536u);
            uint32_t bsw = (((uint32_t)(ks * 2) + bk) ^ ksw) << 4;
#pragma unroll
            for (int jj = 0; jj < 8; jj++)
                ldsm4(br[jj], bb + (((uint32_t)(16 * jj) + krow) << 7) + bsw);
#pragma unroll
            for (int j = 0; j < 16; j++) mma_f16(acc[j], ah, &br[j >> 1][(j & 1) * 2]);
#pragma unroll
            for (int j = 0; j < 16; j++) mma_f16(acc[j], al, &br[j >> 1][(j & 1) * 2]);
        }
    }

    int ci0 = 16 * wid + (L >> 2);
    float b0 = gb[ci0], b1 = gb[ci0 + 8];
    __half* o = d_gxf + ((size_t)b * CIc + ci0) * NNp + n0;
#pragma unroll
    for (int j = 0; j < 16; j++) {
        int col = 8 * j + 2 * (L & 3);
        __half2 p = __floats2half2_rn(acc[j][0] + b0, acc[j][1] + b0);
        *reinterpret_cast<__half2*>(o + col) = p;
        p = __floats2half2_rn(acc[j][2] + b1, acc[j][3] + b1);
        *reinterpret_cast<__half2*>(o + 8 * NNp + col) = p;
    }
}

// ---------------- wy[b][c][n] = W_w y + W_b  (A split, B single) + BN partials -
__global__ __launch_bounds__(256, 1) void k_wy_mma(const float* __restrict__ Wb) {
    extern __shared__ char sm[];
    uint32_t sb = smem_u32(sm);
    int t = threadIdx.x, L = t & 31, wid = t >> 5;
    int bx = blockIdx.x;
    int b  = bx >> 5;
    int n0 = (bx & 31) << 7;
    const __half* Bh = d_yf + ((size_t)b * NNp + n0) * CIc;

#pragma unroll
    for (int i = 0; i < 16; i++) {
        int e = t + (i << 8);
        int r = e >> 4, u = e & 15;
        uint32_t su = (uint32_t)(u ^ (r & 7));
        cp16(sb + GXA_H + ((uint32_t)r << 8) + (su << 4), d_Wwh + (size_t)r * CIc + u * 8);
        cp16(sb + GXA_L + ((uint32_t)r << 8) + (su << 4), d_Wwl + (size_t)r * CIc + u * 8);
    }
    cp_chunkS(sb + GXB0, Bh, CIc);
    cp_commit();

    uint32_t arow0 = (uint32_t)(32 * wid + (L & 15));
    uint32_t qk8   = (uint32_t)(L >> 4);
    uint32_t krow  = (uint32_t)((L & 7) + ((L >> 4) << 3));
    uint32_t ksw   = krow & 7;
    uint32_t bk    = (uint32_t)((L >> 3) & 1);

    float acc[2][16][4];
#pragma unroll
    for (int mt = 0; mt < 2; mt++)
#pragma unroll
        for (int j = 0; j < 16; j++)
#pragma unroll
            for (int q = 0; q < 4; q++) acc[mt][j][q] = 0.f;

    for (int kc = 0; kc < 2; kc++) {
        cp_wait0();
        __syncthreads();
        if (kc < 1) {
            cp_chunkS(sb + GXB1, Bh + 64, CIc);
            cp_commit();
        }
        uint32_t bb = sb + (kc ? GXB1 : GXB0);
#pragma unroll
        for (int ks = 0; ks < 4; ks++) {
            uint32_t ah[2][4], al[2][4], br[8][4];
            uint32_t ku = (uint32_t)(kc * 8 + ks * 2) + qk8;
#pragma unroll
            for (int mt = 0; mt < 2; mt++) {
                uint32_t ar = arow0 + 16u * (uint32_t)mt;
                uint32_t qa = sb + GXA_H + (ar << 8) + ((ku ^ (ar & 7)) << 4);
                ldsm4(ah[mt], qa);
                ldsm4(al[mt], qa + 65536u);
            }
            uint32_t bsw = (((uint32_t)(ks * 2) + bk) ^ ksw) << 4;
#pragma unroll
            for (int jj = 0; jj < 8; jj++)
                ldsm4(br[jj], bb + (((uint32_t)(16 * jj) + krow) << 7) + bsw);
#pragma unroll
            for (int mt = 0; mt < 2; mt++)
#pragma unroll
                for (int j = 0; j < 16; j++)
                    mma_f16(acc[mt][j], ah[mt], &br[j >> 1][(j & 1) * 2]);
#pragma unroll
            for (int mt = 0; mt < 2; mt++)
#pragma unroll
                for (int j = 0; j < 16; j++)
                    mma_f16(acc[mt][j], al[mt], &br[j >> 1][(j & 1) * 2]);
        }
    }

    int c0 = 32 * wid + (L >> 2);
    float ps[4], pq[4];
#pragma unroll
    for (int i = 0; i < 4; i++) { ps[i] = 0.f; pq[i] = 0.f; }

#pragma unroll
    for (int mt = 0; mt < 2; mt++) {
        int ca = c0 + 16 * mt, cb = ca + 8;
        float ba = Wb[ca], bb2 = Wb[cb];
        __half* oa = d_wyh + ((size_t)b * Cc + ca) * NNp + n0;
        __half* ob = d_wyh + ((size_t)b * Cc + cb) * NNp + n0;
#pragma unroll
        for (int j = 0; j < 16; j++) {
            int col = 8 * j + 2 * (L & 3);
            float v0 = acc[mt][j][0] + ba;
            float v1 = acc[mt][j][1] + ba;
            float v2 = acc[mt][j][2] + bb2;
            float v3 = acc[mt][j][3] + bb2;
            *reinterpret_cast<__half2*>(oa + col) = __floats2half2_rn(v0, v1);
            *reinterpret_cast<__half2*>(ob + col) = __floats2half2_rn(v2, v3);
            ps[mt * 2]     += v0 + v1;
            pq[mt * 2]     += v0 * v0 + v1 * v1;
            ps[mt * 2 + 1] += v2 + v3;
            pq[mt * 2 + 1] += v2 * v2 + v3 * v3;
        }
    }
#pragma unroll
    for (int i = 0; i < 4; i++) {
        ps[i] += __shfl_xor_sync(0xffffffffu, ps[i], 1);
        ps[i] += __shfl_xor_sync(0xffffffffu, ps[i], 2);
        pq[i] += __shfl_xor_sync(0xffffffffu, pq[i], 1);
        pq[i] += __shfl_xor_sync(0xffffffffu, pq[i], 2);
    }
    if ((L & 3) == 0) {
#pragma unroll
        for (int mt = 0; mt < 2; mt++)
#pragma unroll
            for (int qh = 0; qh < 2; qh++) {
                int c = c0 + 16 * mt + 8 * qh;
                d_psum[bx * Cc + c] = ps[mt * 2 + qh];
                d_psq [bx * Cc + c] = pq[mt * 2 + qh];
            }
    }
}

// ---------------- flash attention: single fp16; 2-sync/tile pipeline ----------
// SMEM: Q 64KB @0; K 64KB @65536 (512B rows); V0 32KB @131072; V1 32KB @163840.
#define SQH   0u
#define SKK   65536u
#define SV0   131072u
#define SV1   163840u
#define FSMEM 196608

__global__ __launch_bounds__(256, 1) void k_flash_mma() {
    extern __shared__ char sm[];
    uint32_t sb = smem_u32(sm);
    int t = threadIdx.x;
    int L = t & 31;
    int wid = t >> 5;                  // warp owns rows 16*wid .. +15
    int b  = blockIdx.y;
    int m0 = blockIdx.x * 128;

    const __half* xh = d_xfh + (size_t)b * NNp * Cc;
    const __half* vf = d_gxf + (size_t)b * CIc * NNp;

    // prologue: [Q + K(t0)] -> group1; V(t0)->SV0 -> group2
    cp_tile256(sb + SQH, xh + (size_t)m0 * Cc, Cc);
    cp_tile256(sb + SKK, xh, Cc);
    cp_commit();
    cp_tile128(sb + SV0, vf, NNp);
    cp_commit();

    uint32_t qrow = (uint32_t)(16 * wid + (L & 15));
    uint32_t qsw  = qrow & 7;
    uint32_t qk8  = (uint32_t)(L >> 4);
    uint32_t krow = (uint32_t)((L & 7) + ((L >> 4) << 3));
    uint32_t ksw  = krow & 7;
    uint32_t bk   = (uint32_t)((L >> 3) & 1);

    float Y[16][4];
    float rs0 = 0.f, rs1 = 0.f;
#pragma unroll
    for (int j = 0; j < 16; j++)
#pragma unroll
        for (int q = 0; q < 4; q++) Y[j][q] = 0.f;

    for (int kt = 0; kt < NNp; kt += 128) {
        int ti = kt >> 7;
        int kt2 = (kt + 128) & (NNp - 1);
        uint32_t svr = sb + ((ti & 1) ? SV1 : SV0);       // this tile's V
        uint32_t svw = sb + ((ti & 1) ? SV0 : SV1);       // next tile's V dest

        float S[16][4];
#pragma unroll
        for (int j = 0; j < 16; j++)
#pragma unroll
            for (int q = 0; q < 4; q++) S[j][q] = 0.f;

        // ---- K(t) ready (V may still be in flight) ----
        cp_wait1();
        __syncthreads();

        // ---- QK over full 256 c ----
#pragma unroll
        for (int ks = 0; ks < 16; ks++) {
            uint32_t ah[4], br[8][4];
            uint32_t qunit = (uint32_t)(ks * 2) + qk8;
            ldsm4(ah, sb + SQH + (qrow << 9) + ((qunit ^ qsw) << 4));
            uint32_t bunit = (uint32_t)(ks * 2) + bk;       // B-fragment uses bk, not qk8
            uint32_t bsw = (bunit ^ ksw) << 4;
#pragma unroll
            for (int jj = 0; jj < 8; jj++)
                ldsm4(br[jj], sb + SKK + (((uint32_t)(16 * jj) + krow) << 9) + bsw);
#pragma unroll
            for (int j = 0; j < 16; j++) mma_f16(S[j], ah, &br[j >> 1][(j & 1) * 2]);
        }

        // ---- V(t) ready + all warps done reading K ----
        cp_wait0();
        __syncthreads();

        // ---- issue next tile's K then V ----
        cp_tile256(sb + SKK, xh + (size_t)kt2 * Cc, Cc);
        cp_commit();
        cp_tile128(svw, vf + kt2, NNp);
        cp_commit();

        // ---- exp + PV ----
#pragma unroll
        for (int ks = 0; ks < 8; ks++) {
            float e00 = __expf(S[2 * ks][0]);
            float e01 = __expf(S[2 * ks][1]);
            float e02 = __expf(S[2 * ks][2]);
            float e03 = __expf(S[2 * ks][3]);
            float e10 = __expf(S[2 * ks + 1][0]);
            float e11 = __expf(S[2 * ks + 1][1]);
            float e12 = __expf(S[2 * ks + 1][2]);
            float e13 = __expf(S[2 * ks + 1][3]);
            rs0 += e00 + e01 + e10 + e11;
            rs1 += e02 + e03 + e12 + e13;
            uint32_t PH[4];
            __half2 hp;
            hp = __floats2half2_rn(e00, e01); PH[0] = *reinterpret_cast<uint32_t*>(&hp);
            hp = __floats2half2_rn(e02, e03); PH[1] = *reinterpret_cast<uint32_t*>(&hp);
            hp = __floats2half2_rn(e10, e11); PH[2] = *reinterpret_cast<uint32_t*>(&hp);
            hp = __floats2half2_rn(e12, e13); PH[3] = *reinterpret_cast<uint32_t*>(&hp);

            uint32_t bv[8][4];
            uint32_t vsw = ((((uint32_t)(ks * 2) + bk) ^ ksw) << 4);
#pragma unroll
            for (int jj = 0; jj < 8; jj++)
                ldsm4(bv[jj], svr + (((uint32_t)(16 * jj) + krow) << 8) + vsw);
#pragma unroll
            for (int j = 0; j < 16; j++) mma_f16(Y[j], PH, &bv[j >> 1][(j & 1) * 2]);
        }
    }

    // epilogue: rowsums within warp; single-fp16 store of y
    rs0 += __shfl_xor_sync(0xffffffffu, rs0, 1);
    rs0 += __shfl_xor_sync(0xffffffffu, rs0, 2);
    rs1 += __shfl_xor_sync(0xffffffffu, rs1, 1);
    rs1 += __shfl_xor_sync(0xffffffffu, rs1, 2);
    float inv0 = 1.f / rs0;
    float inv1 = 1.f / rs1;

    int r0 = 16 * wid + (L >> 2);
    __half* yf0 = d_yf + ((size_t)b * NNp + m0 + r0) * CIc;
#pragma unroll
    for (int j = 0; j < 16; j++) {
        int col = 8 * j + 2 * (L & 3);
        __half2 p = __floats2half2_rn(Y[j][0] * inv0, Y[j][1] * inv0);
        *reinterpret_cast<__half2*>(yf0 + col) = p;
        p = __floats2half2_rn(Y[j][2] * inv1, Y[j][3] * inv1);
        *reinterpret_cast<__half2*>(yf0 + 8 * CIc + col) = p;
    }
}

// ---------------- BN reduce over 128 per-block partials -------------------------
__global__ void k_bnreduce() {
    int c = threadIdx.x;               // 256 threads, 1 block
    float s = 0.f, q = 0.f;
#pragma unroll 8
    for (int bkx = 0; bkx < 128; bkx++) {
        s += d_psum[bkx * Cc + c];
        q += d_psq [bkx * Cc + c];
    }
    d_sum[c] = s;
    d_sqs[c] = q;
}

// ---------------- BN apply + residual (elementwise; wyh is [c][n] fp16) -------
__global__ void k_bnfinal2(const float* __restrict__ x,
                           const float* __restrict__ gamma,
                           const float* __restrict__ beta,
                           float* __restrict__ out) {
    size_t base = ((size_t)blockIdx.x * 256 + threadIdx.x) * 4;
    int c = (int)((base >> 12) & 255);
    const float invn = 1.f / (float)(Bq * NNp);
    float mean = d_sum[c] * invn;
    float var  = d_sqs[c] * invn - mean * mean;
    float rsv  = rsqrtf(var + EPSc);
    float g    = gamma[c] * rsv;
    float be   = beta[c] - mean * g;
    const __half2* w2 = reinterpret_cast<const __half2*>(d_wyh + base);
    float2 wa = __half22float2(w2[0]);
    float2 wb = __half22float2(w2[1]);
    float4 xv = *reinterpret_cast<const float4*>(x + base);
    float4 o;
    o.x = wa.x * g + be + xv.x;
    o.y = wa.y * g + be + xv.y;
    o.z = wb.x * g + be + xv.z;
    o.w = wb.y * g + be + xv.w;
    *reinterpret_cast<float4*>(out + base) = o;
}

// ---------------- launch -------------------------------------------------------
extern "C" void kernel_launch(void* const* d_in, const int* in_sizes, int n_in,
                              void* d_out, int out_size) {
    const float* x     = (const float*)d_in[0];
    const float* g_w   = (const float*)d_in[1];
    const float* g_b   = (const float*)d_in[2];
    const float* W_w   = (const float*)d_in[3];
    const float* W_b   = (const float*)d_in[4];
    const float* gamma = (const float*)d_in[5];
    const float* beta  = (const float*)d_in[6];
    float* out = (float*)d_out;

    (void)in_sizes; (void)n_in; (void)out_size;

    cudaFuncSetAttribute(k_flash_mma, cudaFuncAttributeMaxDynamicSharedMemorySize, FSMEM);
    cudaFuncSetAttribute(k_gx_mma, cudaFuncAttributeMaxDynamicSharedMemorySize, GSMEM);
    cudaFuncSetAttribute(k_wy_mma, cudaFuncAttributeMaxDynamicSharedMemorySize, GSMEM);

    k_transpose<<<dim3(NNp / 32, Cc / 32, Bq), dim3(32, 8)>>>(x);
    k_split_w<<<128, 256>>>(g_w, W_w);
    k_gx_mma<<<128, 256, GSMEM>>>(g_b);
    k_flash_mma<<<dim3(NNp / 128, Bq), 256, FSMEM>>>();
    k_wy_mma<<<128, 256, GSMEM>>>(W_b);
    k_bnreduce<<<1, 256>>>();
    k_bnfinal2<<<4096, 256>>>(x, gamma, beta, out);
}